// round 13
// baseline (speedup 1.0000x reference)
#include <cuda_runtime.h>
#include <cuda_fp16.h>
#include <math.h>

#define BB 16
#define SS 16
#define VV 64
#define EE 64
#define HH 8
#define NL 4
#define DFF 2048
#define LL 1024
#define ML (BB*LL)
#define SPH 72   // smem row stride in halves (64 data + 8 pad) = 144 bytes

// ---------------- scratch ----------------
__device__ float g_x[ML * EE];            // fp32 residual stream
__device__ __half g_xh[ML * EE];          // fp16 copy of x
__device__ __half g_qh[ML * EE];          // Q fp16 pre-scaled [B][H][L][8]
__device__ __half g_kh[ML * EE];          // K fp16 [B][H][L][8]
__device__ __half g_vh[ML * EE];          // V fp16 [B][H][L][8]
__device__ __half g_attnh[ML * EE];       // attention output (fp16)
__device__ unsigned char g_zero[ML];

// pre-converted transposed fp16 weights ([n][k])
__device__ __align__(256) __half g_qkvT[NL * 192 * 64];
__device__ __align__(256) __half g_woT[NL * 64 * 64];
__device__ __align__(256) __half g_w1T[NL * DFF * 64];
__device__ __align__(256) __half g_w2T[NL * DFF * 64];

// ---------------- helpers ----------------
__device__ __forceinline__ unsigned pack2h(float a, float b) {
    __half2 h = __floats2half2_rn(a, b);
    return *(unsigned*)&h;
}
__device__ __forceinline__ void mma_f16(float* c, const unsigned* a, const unsigned* b) {
    asm volatile(
        "mma.sync.aligned.m16n8k16.row.col.f32.f16.f16.f32 "
        "{%0,%1,%2,%3}, {%4,%5,%6,%7}, {%8,%9}, {%0,%1,%2,%3};\n"
        : "+f"(c[0]), "+f"(c[1]), "+f"(c[2]), "+f"(c[3])
        : "r"(a[0]), "r"(a[1]), "r"(a[2]), "r"(a[3]), "r"(b[0]), "r"(b[1]));
}
__device__ __forceinline__ void ldsm_x4(unsigned* r, unsigned addr) {
    asm volatile("ldmatrix.sync.aligned.m8n8.x4.shared.b16 {%0,%1,%2,%3}, [%4];\n"
        : "=r"(r[0]), "=r"(r[1]), "=r"(r[2]), "=r"(r[3]) : "r"(addr));
}
__device__ __forceinline__ float warp_sum32(float v) {
#pragma unroll
    for (int o = 16; o > 0; o >>= 1) v += __shfl_xor_sync(0xffffffffu, v, o);
    return v;
}
#define CP_ASYNC16(dst, src) \
    asm volatile("cp.async.ca.shared.global [%0], [%1], 16;\n" :: "r"(dst), "l"(src))
#define CP_COMMIT() asm volatile("cp.async.commit_group;\n")
#define CP_WAIT1()  asm volatile("cp.async.wait_group 1;\n")
#define CP_WAIT0()  asm volatile("cp.async.wait_group 0;\n")

// ---------------- weight prep: coalesced tiled transpose ----------------
__global__ __launch_bounds__(256) void prep_weights(const float* __restrict__ Wqkv,
                                                    const float* __restrict__ Wo,
                                                    const float* __restrict__ W1,
                                                    const float* __restrict__ W2)
{
    __shared__ float s[64 * 65];
    int tid = threadIdx.x;
    int bx = blockIdx.x, which = blockIdx.y;

    if (which == 0) {
        if (bx >= NL * 6) return;
        int layer = bx / 6, n0 = (bx % 6) * 32;
        for (int i = tid; i < 2048; i += 256) {
            int k = i >> 5, n = i & 31;
            s[k * 33 + n] = Wqkv[(size_t)layer * 12288 + k * 192 + n0 + n];
        }
        __syncthreads();
        for (int i = tid; i < 2048; i += 256) {
            int n = i >> 6, k = i & 63;
            g_qkvT[(size_t)layer * 12288 + (n0 + n) * 64 + k] = __float2half_rn(s[k * 33 + n]);
        }
    } else if (which == 1) {
        if (bx >= NL * 2) return;
        int layer = bx / 2, n0 = (bx % 2) * 32;
        for (int i = tid; i < 2048; i += 256) {
            int k = i >> 5, n = i & 31;
            s[k * 33 + n] = Wo[(size_t)layer * 4096 + k * 64 + n0 + n];
        }
        __syncthreads();
        for (int i = tid; i < 2048; i += 256) {
            int n = i >> 6, k = i & 63;
            g_woT[(size_t)layer * 4096 + (n0 + n) * 64 + k] = __float2half_rn(s[k * 33 + n]);
        }
    } else if (which == 2) {
        if (bx >= NL * 64) return;
        int layer = bx / 64, n0 = (bx % 64) * 32;
        for (int i = tid; i < 2048; i += 256) {
            int k = i >> 5, n = i & 31;
            s[k * 33 + n] = W1[(size_t)layer * DFF * 64 + k * DFF + n0 + n];
        }
        __syncthreads();
        for (int i = tid; i < 2048; i += 256) {
            int n = i >> 6, k = i & 63;
            g_w1T[(size_t)layer * DFF * 64 + (n0 + n) * 64 + k] = __float2half_rn(s[k * 33 + n]);
        }
    } else {
        if (bx >= NL * 32) return;
        int layer = bx / 32, c = bx % 32;
        for (int i = tid; i < 4096; i += 256) {
            int kl = i >> 6, n = i & 63;
            s[kl * 65 + n] = W2[(size_t)layer * DFF * 64 + (c * 64 + kl) * 64 + n];
        }
        __syncthreads();
        for (int i = tid; i < 4096; i += 256) {
            int n = i >> 6, kl = i & 63;
            g_w2T[(size_t)layer * DFF * 64 + c * 4096 + n * 64 + kl] = __float2half_rn(s[kl * 65 + n]);
        }
    }
}

// ---------------- embed ----------------
__global__ void embed_kernel(const float* __restrict__ features,
                             const int* __restrict__ overlap_tag,
                             const int* __restrict__ poi_id,
                             const float* __restrict__ W_raw,
                             const float* __restrict__ b_raw,
                             const float* __restrict__ pos_tab,
                             const float* __restrict__ type_tab,
                             const float* __restrict__ poi_tab,
                             const float* __restrict__ overlap_tab,
                             const float* __restrict__ W_comb,
                             const float* __restrict__ b_comb,
                             float* __restrict__ x,
                             __half* __restrict__ xh,
                             unsigned char* __restrict__ zero_mask)
{
    int bl = blockIdx.x;
    int l  = bl & (LL - 1);
    int s  = l >> 6;
    int v  = l & 63;
    int tid = threadIdx.x;  // 64

    __shared__ float concat[80];
    const float* f = features + (size_t)bl * 3;
    float f0 = f[0], f1 = f[1], f2 = f[2];

    concat[tid] = f0 * W_raw[tid] + f1 * W_raw[64 + tid] + f2 * W_raw[128 + tid] + b_raw[tid];
    if (tid < 8) {
        int ov = overlap_tag[bl];
        concat[64 + tid] = (ov == 0) ? 0.0f : overlap_tab[ov * 8 + tid];
        int poi = poi_id[bl];
        concat[72 + tid] = (poi == 0) ? 0.0f : poi_tab[poi * 8 + tid];
    }
    if (tid == 0) zero_mask[bl] = (f0 + f1 + f2 == 0.0f) ? 1 : 0;
    __syncthreads();

    float acc = b_comb[tid];
#pragma unroll
    for (int j = 0; j < 80; j++) acc += concat[j] * W_comb[j * EE + tid];
    acc += pos_tab[s * EE + tid] + type_tab[v * EE + tid];
    x[(size_t)bl * EE + tid] = acc;
    xh[(size_t)bl * EE + tid] = __float2half_rn(acc);
}

// ---------------- QKV GEMM (fp16): Q pre-scaled fp16, K/V fp16, all permuted ----------------
__global__ __launch_bounds__(256) void gemm_qkv(const __half* __restrict__ Xh,
                                                const __half* __restrict__ WT,
                                                const float* __restrict__ bias,
                                                __half* __restrict__ Qo,
                                                __half* __restrict__ Ko,
                                                __half* __restrict__ Vo)
{
    __shared__ __align__(16) __half As[128 * SPH];
    __shared__ __align__(16) __half Ws[64 * SPH];

    int tid = threadIdx.x;
    int w = tid >> 5, lane = tid & 31;
    int wm = w >> 1, wn = w & 1;
    int rm = wm * 32, cn = wn * 32;
    int row0 = blockIdx.y * 128;
    int sel = blockIdx.x;
    int gr = lane >> 2, gc = (lane & 3) * 2;

    for (int i = tid; i < 1024; i += 256) {
        int r = i >> 3, seg = i & 7;
        *(uint4*)&As[r * SPH + seg * 8] = *(const uint4*)&Xh[(size_t)(row0 + r) * 64 + seg * 8];
    }
    const __half* src = WT + sel * 4096;
    for (int i = tid; i < 512; i += 256) {
        int n = i >> 3, seg = i & 7;
        *(uint4*)&Ws[n * SPH + seg * 8] = *(const uint4*)&src[n * 64 + seg * 8];
    }
    __syncthreads();

    float acc[2][4][4];
#pragma unroll
    for (int i = 0; i < 2; i++)
#pragma unroll
        for (int j = 0; j < 4; j++)
#pragma unroll
            for (int r = 0; r < 4; r++) acc[i][j][r] = 0.0f;

#pragma unroll
    for (int kt = 0; kt < 4; kt++) {
        int kk = kt * 16;
        unsigned a[2][4], b[4][2];
#pragma unroll
        for (int mi = 0; mi < 2; mi++) {
            int r = rm + mi * 16;
            a[mi][0] = *(unsigned*)&As[(r + gr) * SPH + kk + gc];
            a[mi][1] = *(unsigned*)&As[(r + gr + 8) * SPH + kk + gc];
            a[mi][2] = *(unsigned*)&As[(r + gr) * SPH + kk + gc + 8];
            a[mi][3] = *(unsigned*)&As[(r + gr + 8) * SPH + kk + gc + 8];
        }
#pragma unroll
        for (int ni = 0; ni < 4; ni++) {
            int n = cn + ni * 8 + gr;
            b[ni][0] = *(unsigned*)&Ws[n * SPH + kk + gc];
            b[ni][1] = *(unsigned*)&Ws[n * SPH + kk + gc + 8];
        }
#pragma unroll
        for (int mi = 0; mi < 2; mi++)
#pragma unroll
            for (int ni = 0; ni < 4; ni++)
                mma_f16(acc[mi][ni], a[mi], b[ni]);
    }

    int b = row0 >> 10;
    const float qscale = (sel == 0) ? 0.35355339059327373f : 1.0f;
    __half* outp = (sel == 0) ? Qo : ((sel == 1) ? Ko : Vo);
#pragma unroll
    for (int mi = 0; mi < 2; mi++) {
        int r0 = rm + mi * 16 + gr;
        int l0 = (row0 + r0) & (LL - 1);
#pragma unroll
        for (int ni = 0; ni < 4; ni++) {
            int loc = cn + ni * 8 + gc;
            int h = loc >> 3, d = loc & 7;
            float b0 = bias[sel * 64 + loc], b1v = bias[sel * 64 + loc + 1];
            size_t base = ((size_t)(b * 8 + h) * LL);
            *(unsigned*)&outp[(base + l0) * 8 + d] =
                pack2h((acc[mi][ni][0] + b0) * qscale, (acc[mi][ni][1] + b1v) * qscale);
            *(unsigned*)&outp[(base + l0 + 8) * 8 + d] =
                pack2h((acc[mi][ni][2] + b0) * qscale, (acc[mi][ni][3] + b1v) * qscale);
        }
    }
}

// ---------------- attention: fp16 K/V/Q, 4 adjacent queries/thread, 256 threads ----------------
#define ATTN_SMEM (32768 + 1024)

__device__ __forceinline__ float dot_h2(const __half2* q2, const uint4& kr) {
    const __half2* kh = (const __half2*)&kr;
    __half2 d = __hmul2(q2[0], kh[0]);
    d = __hfma2(q2[1], kh[1], d);
    d = __hfma2(q2[2], kh[2], d);
    d = __hfma2(q2[3], kh[3], d);
    return __low2float(d) + __high2float(d);
}

__global__ __launch_bounds__(256) void attn_kernel(const __half* __restrict__ Qg,
                                                   const __half* __restrict__ Kg,
                                                   const __half* __restrict__ Vg,
                                                   const unsigned char* __restrict__ zero_mask,
                                                   __half* __restrict__ out)
{
    extern __shared__ char smc[];
    __half* Ks = (__half*)smc;
    __half* Vs = (__half*)(smc + 16384);
    unsigned char* zs = (unsigned char*)(smc + 32768);

    int bh = blockIdx.x;                  // 128 blocks
    int b = bh >> 3, h = bh & 7;
    int tid = threadIdx.x;                // 256
    size_t base = (size_t)bh * LL * 8;

    for (int i = tid; i < 1024; i += 256) {
        ((uint4*)Ks)[i] = ((const uint4*)(Kg + base))[i];
        ((uint4*)Vs)[i] = ((const uint4*)(Vg + base))[i];
    }
    for (int i = tid; i < 1024; i += 256) zs[i] = zero_mask[b * LL + i];
    __syncthreads();

    int qb0 = tid * 4;                    // 4 adjacent queries, same t-block
    int tq = qb0 >> 6;
    int vq = qb0 & 63;

    uint4 qr[4];
#pragma unroll
    for (int i = 0; i < 4; i++) qr[i] = *(const uint4*)&Qg[base + (qb0 + i) * 8];

    float sQ[4] = {0.0f, 0.0f, 0.0f, 0.0f};
    float accF[4][8];
#pragma unroll
    for (int i = 0; i < 4; i++)
#pragma unroll
        for (int d = 0; d < 8; d++) accF[i][d] = 0.0f;
    const __half2 hz = __floats2half2_rn(0.0f, 0.0f);

    // block-diagonal part: 64 shared keys, 4 chunks of 16 with fp32 promotion
    int kb = tq << 6;
#pragma unroll
    for (int ch = 0; ch < 4; ch++) {
        __half2 a[4][4];
#pragma unroll
        for (int i = 0; i < 4; i++)
#pragma unroll
            for (int d = 0; d < 4; d++) a[i][d] = hz;
#pragma unroll
        for (int j = 0; j < 16; j++) {
            int k = kb + ch * 16 + j;
            uint4 kr = *(const uint4*)&Ks[k * 8];
            float w0 = __expf(dot_h2((const __half2*)&qr[0], kr));
            float w1 = __expf(dot_h2((const __half2*)&qr[1], kr));
            float w2 = __expf(dot_h2((const __half2*)&qr[2], kr));
            float w3 = __expf(dot_h2((const __half2*)&qr[3], kr));
            if (zs[k]) { w0 = 0.0f; w1 = 0.0f; w2 = 0.0f; w3 = 0.0f; }
            sQ[0] += w0; sQ[1] += w1; sQ[2] += w2; sQ[3] += w3;
            __half2 wh[4];
            wh[0] = __float2half2_rn(w0);
            wh[1] = __float2half2_rn(w1);
            wh[2] = __float2half2_rn(w2);
            wh[3] = __float2half2_rn(w3);
            uint4 vr = *(const uint4*)&Vs[k * 8];
            const __half2* vh = (const __half2*)&vr;
#pragma unroll
            for (int i = 0; i < 4; i++)
#pragma unroll
                for (int d = 0; d < 4; d++)
                    a[i][d] = __hfma2(wh[i], vh[d], a[i][d]);
        }
#pragma unroll
        for (int i = 0; i < 4; i++)
#pragma unroll
            for (int d = 0; d < 4; d++) {
                float2 fa = __half22float2(a[i][d]);
                accF[i][2 * d] += fa.x;
                accF[i][2 * d + 1] += fa.y;
            }
    }

    // same-type columns: 15 keys per query (separate key per query)
#pragma unroll
    for (int i = 0; i < 4; i++) {
        __half2 a[4] = {hz, hz, hz, hz};
        const __half2* q2 = (const __half2*)&qr[i];
#pragma unroll
        for (int t = 0; t < 16; t++) {
            if (t == tq) continue;
            int k = (t << 6) + vq + i;
            uint4 kr = *(const uint4*)&Ks[k * 8];
            float wv = __expf(dot_h2(q2, kr));
            wv = zs[k] ? 0.0f : wv;
            sQ[i] += wv;
            __half2 wh = __float2half2_rn(wv);
            uint4 vr = *(const uint4*)&Vs[k * 8];
            const __half2* vh = (const __half2*)&vr;
#pragma unroll
            for (int d = 0; d < 4; d++) a[d] = __hfma2(wh, vh[d], a[d]);
        }
#pragma unroll
        for (int d = 0; d < 4; d++) {
            float2 fa = __half22float2(a[d]);
            accF[i][2 * d] += fa.x;
            accF[i][2 * d + 1] += fa.y;
        }
    }

#pragma unroll
    for (int i = 0; i < 4; i++) {
        float inv = 1.0f / sQ[i];
        __half* o = out + ((size_t)(b * LL + qb0 + i)) * EE + h * 8;
        uint4 pk;
        pk.x = pack2h(accF[i][0] * inv, accF[i][1] * inv);
        pk.y = pack2h(accF[i][2] * inv, accF[i][3] * inv);
        pk.z = pack2h(accF[i][4] * inv, accF[i][5] * inv);
        pk.w = pack2h(accF[i][6] * inv, accF[i][7] * inv);
        *(uint4*)o = pk;
    }
}

// ---------------- fused Wo+LN1+FFN+LN2 (fp16), 128 rows/block, 256 thr ----------------
// smem layout (bytes):
//   XS:   0      .. 18432   attnh tile, then post-LN1 x
//   HS0:  18432  .. 36864   Wo weights / o-proj / ffn h (even chunks)
//   HS1:  36864  .. 55296   ffn h (odd chunks)
//   WS:   55296  .. 92160   (2 stages * 18432)
//   buf:  aliases WS (128*65*4 = 33280 <= 36864), used after chunk loop
#define XS_OFF 0
#define HS_OFF 18432
#define HS_STRIDE 18432
#define WS_OFF 55296
#define WS_STRIDE 18432
#define FBUF_OFF 55296
#define FFN_SMEM 92160

__global__ __launch_bounds__(256) void wo_ffn_fused(const __half* __restrict__ attnh,
                                                    const __half* __restrict__ woT,
                                                    const float* __restrict__ bo,
                                                    const float* __restrict__ ln1_s,
                                                    const float* __restrict__ ln1_b,
                                                    const __half* __restrict__ w1T,
                                                    const __half* __restrict__ w2T,
                                                    const float* __restrict__ b1,
                                                    const float* __restrict__ b2,
                                                    const float* __restrict__ ln2_s,
                                                    const float* __restrict__ ln2_b,
                                                    float* __restrict__ x,
                                                    __half* __restrict__ xh)
{
    extern __shared__ __align__(16) char sm[];
    __half* XS = (__half*)(sm + XS_OFF);
    __half* HS0 = (__half*)(sm + HS_OFF);
    float* buf = (float*)(sm + FBUF_OFF);
    unsigned smem_base = (unsigned)__cvta_generic_to_shared(sm);

    int tid = threadIdx.x;
    int w = tid >> 5, lane = tid & 31;
    int wm = w >> 1, wn = w & 1;
    int rm = wm * 32, cn = wn * 32;
    int row0 = blockIdx.x * 128;
    int gr = lane >> 2, gc = (lane & 3) * 2;

    int a_row = (lane & 7) + ((lane >> 3) & 1) * 8;
    int a_col = (lane >> 4) * 8;
    int b_row = (lane & 7) + ((lane >> 4) & 1) * 8;
    int b_col = ((lane >> 3) & 1) * 8;
    unsigned aoff = (unsigned)(((rm + a_row) * SPH + a_col) * 2);
    unsigned boff = (unsigned)(((cn + b_row) * SPH + b_col) * 2);

    unsigned xs_b = smem_base + XS_OFF;
    unsigned hs_b = smem_base + HS_OFF;

    // group A: attnh tile -> XS + Wo weights -> HS0
    {
        int r = tid >> 1, sb = (tid & 1) * 4;
        const __half* src = attnh + (size_t)(row0 + r) * 64;
#pragma unroll
        for (int j = 0; j < 4; j++)
            CP_ASYNC16(xs_b + r * 144 + (sb + j) * 16, src + (sb + j) * 8);
        int n = tid >> 2, seg0 = (tid & 3) * 2;
        CP_ASYNC16(hs_b + n * 144 + seg0 * 16, woT + n * 64 + seg0 * 8);
        CP_ASYNC16(hs_b + n * 144 + (seg0 + 1) * 16, woT + n * 64 + (seg0 + 1) * 8);
    }
    CP_COMMIT();

    // group B: ffn chunk 0 -> WS stage 0
    int wr = tid >> 2, ws0 = (tid & 3) * 2;
    unsigned wdst = (unsigned)(wr * 144 + ws0 * 16);
    int wsrc = wr * 64 + ws0 * 8;
    {
        unsigned st = smem_base + WS_OFF;
        CP_ASYNC16(st + wdst, w1T + wsrc);
        CP_ASYNC16(st + wdst + 16, w1T + wsrc + 8);
        CP_ASYNC16(st + 9216 + wdst, w2T + wsrc);
        CP_ASYNC16(st + 9216 + wdst + 16, w2T + wsrc + 8);
    }
    CP_COMMIT();
    CP_WAIT1();           // group A done; group B may still be in flight
    __syncthreads();

    // ---- Wo GEMM ----
    float oacc[2][4][4];
#pragma unroll
    for (int i = 0; i < 2; i++)
#pragma unroll
        for (int j = 0; j < 4; j++)
#pragma unroll
            for (int r = 0; r < 4; r++) oacc[i][j][r] = 0.0f;

#pragma unroll
    for (int kt = 0; kt < 4; kt++) {
        unsigned kko = (unsigned)(kt * 32);
        unsigned a[2][4], bf[2][4];
        ldsm_x4(a[0], xs_b + aoff + kko);
        ldsm_x4(a[1], xs_b + aoff + 16 * 144 + kko);
        ldsm_x4(bf[0], hs_b + boff + kko);
        ldsm_x4(bf[1], hs_b + boff + 16 * 144 + kko);
#pragma unroll
        for (int mi = 0; mi < 2; mi++)
#pragma unroll
            for (int p = 0; p < 2; p++) {
                mma_f16(oacc[mi][p * 2],     a[mi], &bf[p][0]);
                mma_f16(oacc[mi][p * 2 + 1], a[mi], &bf[p][2]);
            }
    }
    __syncthreads();

#pragma unroll
    for (int mi = 0; mi < 2; mi++)
#pragma unroll
        for (int ni = 0; ni < 4; ni++) {
            int cl = cn + ni * 8 + gc;
            float bb0 = bo[cl], bb1 = bo[cl + 1];
            int r0 = rm + mi * 16 + gr;
            *(unsigned*)&HS0[r0 * SPH + cl] = pack2h(oacc[mi][ni][0] + bb0, oacc[mi][ni][1] + bb1);
            *(unsigned*)&HS0[(r0 + 8) * SPH + cl] = pack2h(oacc[mi][ni][2] + bb0, oacc[mi][ni][3] + bb1);
        }
    __syncthreads();

    // ---- LN1: x1 = LN(o + x_res); keep fp32 in regs, write fp16 to XS ----
    float xr0[16], xr1[16];
#pragma unroll
    for (int rr = 0; rr < 16; rr++) {
        int row = w * 16 + rr;
        size_t go = (size_t)(row0 + row) * 64;
        float y0 = __half2float(HS0[row * SPH + lane]) + x[go + lane];
        float y1 = __half2float(HS0[row * SPH + lane + 32]) + x[go + lane + 32];
        float mean = warp_sum32(y0 + y1) * (1.0f / 64.0f);
        float d0 = y0 - mean, d1 = y1 - mean;
        float var = warp_sum32(d0 * d0 + d1 * d1) * (1.0f / 64.0f);
        float inv = rsqrtf(var + 1e-5f);
        float o0 = d0 * inv * ln1_s[lane] + ln1_b[lane];
        float o1 = d1 * inv * ln1_s[lane + 32] + ln1_b[lane + 32];
        xr0[rr] = o0;
        xr1[rr] = o1;
        XS[row * SPH + lane] = __float2half_rn(o0);
        XS[row * SPH + lane + 32] = __float2half_rn(o1);
    }
    __syncthreads();

    // ---- FFN main loop: double-buffered H, 2 syncs/chunk ----
    float acc2[2][4][4];
#pragma unroll
    for (int i = 0; i < 2; i++)
#pragma unroll
        for (int j = 0; j < 4; j++)
#pragma unroll
            for (int r = 0; r < 4; r++) acc2[i][j][r] = 0.0f;

    for (int c = 0; c < 32; c++) {
        int s = c & 1;
        CP_WAIT0();
        __syncthreads();       // chunk c weights visible; all warps past GEMM2(c-1)

        if (c + 1 < 32) {      // prefetch chunk c+1 (safe: GEMM2(c-1) readers of WS[s^1] are done)
            unsigned st = smem_base + WS_OFF + (s ^ 1) * WS_STRIDE;
            int src = (c + 1) * 4096 + wsrc;
            CP_ASYNC16(st + wdst, w1T + src);
            CP_ASYNC16(st + wdst + 16, w1T + src + 8);
            CP_ASYNC16(st + 9216 + wdst, w2T + src);
            CP_ASYNC16(st + 9216 + wdst + 16, w2T + src + 8);
            CP_COMMIT();
        }

        unsigned w1_b = smem_base + WS_OFF + s * WS_STRIDE;
        unsigned w2_b = w1_b + 9216;
        unsigned hs_c = hs_b + s * HS_STRIDE;
        __half* HSc = (__half*)(sm + HS_OFF + s * HS_STRIDE);

        float hacc[2][4][4];
#pragma unroll
        for (int i = 0; i < 2; i++)
#pragma unroll
            for (int j = 0; j < 4; j++)
#pragma unroll
                for (int r = 0; r < 4; r++) hacc[i][j][r] = 0.0f;

#pragma unroll
        for (int kt = 0; kt < 4; kt++) {
            unsigned kko = (unsigned)(kt * 32);
            unsigned a[2][4], bf[2][4];
            ldsm_x4(a[0], xs_b + aoff + kko);
            ldsm_x4(a[1], xs_b + aoff + 16 * 144 + kko);
            ldsm_x4(bf[0], w1_b + boff + kko);
            ldsm_x4(bf[1], w1_b + boff + 16 * 144 + kko);
#pragma unroll
            for (int mi = 0; mi < 2; mi++)
#pragma unroll
                for (int p = 0; p < 2; p++) {
                    mma_f16(hacc[mi][p * 2],     a[mi], &bf[p][0]);
                    mma_f16(hacc[mi][p * 2 + 1], a[mi], &bf[p][2]);
                }
        }

#pragma unroll
        for (int mi = 0; mi < 2; mi++)
#pragma unroll
            for (int ni = 0; ni < 4; ni++) {
                int cl = cn + ni * 8 + gc;
                int cg = c * 64 + cl;
                float bb0 = b1[cg], bb1 = b1[cg + 1];
                float v0 = fmaxf(hacc[mi][ni][0] + bb0, 0.0f);
                float v1 = fmaxf(hacc[mi][ni][1] + bb1, 0.0f);
                float v2 = fmaxf(hacc[mi][ni][2] + bb0, 0.0f);
                float v3 = fmaxf(hacc[mi][ni][3] + bb1, 0.0f);
                *(unsigned*)&HSc[(rm + mi * 16 + gr) * SPH + cl] = pack2h(v0, v1);
                *(unsigned*)&HSc[(rm + mi * 16 + gr + 8) * SPH + cl] = pack2h(v2, v3);
            }
        __syncthreads();       // H visible

#pragma unroll
        for (int kt = 0; kt < 4; kt++) {
            unsigned kko = (unsigned)(kt * 32);
            unsigned a[2][4], bf[2][4];
            ldsm_x4(a[0], hs_c + aoff + kko);
            ldsm_x4(a[1], hs_c + aoff + 16 * 144 + kko);
            ldsm_x4(bf[0], w2_b + boff + kko);
            ldsm_x4(bf[1], w2_b + boff + 16 * 144 + kko);
#pragma unroll
            for (int mi = 0; mi < 2; mi++)
#pragma unroll
                for (int p = 0; p < 2; p++) {
                    mma_f16(acc2[mi][p * 2],     a[mi], &bf[p][0]);
                    mma_f16(acc2[mi][p * 2 + 1], a[mi], &bf[p][2]);
                }
        }
        // no trailing sync: next chunk's weight sync covers all hazards
    }
    __syncthreads();           // all GEMM2(31) reads of WS done before buf (aliases WS) is written

    // epilogue: + b2 -> buf, + residual(regs), LN2
#pragma unroll
    for (int mi = 0; mi < 2; mi++)
#pragma unroll
        for (int ni = 0; ni < 4; ni++) {
            int cc = cn + ni * 8 + gc;
            float b0 = b2[cc], b1v = b2[cc + 1];
            int r0 = rm + mi * 16 + gr;
            buf[r0 * 65 + cc] = acc2[mi][ni][0] + b0;
            buf[r0 * 65 + cc + 1] = acc2[mi][ni][1] + b1v;
            buf[(r0 + 8) * 65 + cc] = acc2[mi][ni][2] + b0;
            buf[(r0 + 8) * 65 + cc + 1] = acc2[mi][ni][3] + b1v;
        }
    __syncthreads();

#pragma unroll
    for (int rr = 0; rr < 16; rr++) {
        int row = w * 16 + rr;
        size_t go = (size_t)(row0 + row) * 64;
        float y0 = buf[row * 65 + lane] + xr0[rr];
        float y1 = buf[row * 65 + lane + 32] + xr1[rr];
        float mean = warp_sum32(y0 + y1) * (1.0f / 64.0f);
        float d0 = y0 - mean, d1 = y1 - mean;
        float var = warp_sum32(d0 * d0 + d1 * d1) * (1.0f / 64.0f);
        float inv = rsqrtf(var + 1e-5f);
        float o0 = d0 * inv * ln2_s[lane] + ln2_b[lane];
        float o1 = d1 * inv * ln2_s[lane + 32] + ln2_b[lane + 32];
        x[go + lane] = o0;
        x[go + lane + 32] = o1;
        xh[go + lane] = __float2half_rn(o0);
        xh[go + lane + 32] = __float2half_rn(o1);
    }
}

// ---------------- head ----------------
__global__ void head_kernel(const float* __restrict__ x,
                            const float* __restrict__ W_head,
                            const float* __restrict__ b_head,
                            float* __restrict__ out)
{
    int b = blockIdx.x;
    int tid = threadIdx.x;  // 192
    int v = tid / 3, c = tid % 3;
    const float* row = x + ((size_t)(b * LL + (SS - 1) * VV + v)) * EE;
    float acc = b_head[c];
#pragma unroll
    for (int e = 0; e < EE; e++) acc += row[e] * W_head[e * 3 + c];
    out[b * (VV * 3) + tid] = acc;
}

// ---------------- launch ----------------
extern "C" void kernel_launch(void* const* d_in, const int* in_sizes, int n_in,
                              void* d_out, int out_size)
{
    const float* features    = (const float*)d_in[0];
    const int*   overlap_tag = (const int*)d_in[1];
    const int*   poi_id      = (const int*)d_in[2];
    const float* W_raw       = (const float*)d_in[3];
    const float* b_raw       = (const float*)d_in[4];
    const float* pos_tab     = (const float*)d_in[5];
    const float* type_tab    = (const float*)d_in[6];
    const float* poi_tab     = (const float*)d_in[7];
    const float* overlap_tab = (const float*)d_in[8];
    const float* W_comb      = (const float*)d_in[9];
    const float* b_comb      = (const float*)d_in[10];
    const float* Wqkv        = (const float*)d_in[11];
    const float* bqkv        = (const float*)d_in[12];
    const float* Wo          = (const float*)d_in[13];
    const float* bo          = (const float*)d_in[14];
    const float* ln1_s       = (const float*)d_in[15];
    const float* ln1_b       = (const float*)d_in[16];
    const float* W1          = (const float*)d_in[17];
    const float* b1          = (const float*)d_in[18];
    const float* W2          = (const float*)d_in[19];
    const float* b2          = (const float*)d_in[20];
    const float* ln2_s       = (const float*)d_in[21];
    const float* ln2_b       = (const float*)d_in[22];
    const float* W_head      = (const float*)d_in[23];
    const float* b_head      = (const float*)d_in[24];
    float* out = (float*)d_out;

    float *x;
    __half *xh, *qb, *kb, *vb, *attnh, *qkvT, *woT, *w1T, *w2T;
    unsigned char* zero;
    cudaGetSymbolAddress((void**)&x,     g_x);
    cudaGetSymbolAddress((void**)&xh,    g_xh);
    cudaGetSymbolAddress((void**)&qb,    g_qh);
    cudaGetSymbolAddress((void**)&kb,    g_kh);
    cudaGetSymbolAddress((void**)&vb,    g_vh);
    cudaGetSymbolAddress((void**)&attnh, g_attnh);
    cudaGetSymbolAddress((void**)&zero,  g_zero);
    cudaGetSymbolAddress((void**)&qkvT,  g_qkvT);
    cudaGetSymbolAddress((void**)&woT,   g_woT);
    cudaGetSymbolAddress((void**)&w1T,   g_w1T);
    cudaGetSymbolAddress((void**)&w2T,   g_w2T);

    cudaFuncSetAttribute(attn_kernel, cudaFuncAttributeMaxDynamicSharedMemorySize, ATTN_SMEM);
    cudaFuncSetAttribute(wo_ffn_fused, cudaFuncAttributeMaxDynamicSharedMemorySize, FFN_SMEM);

    prep_weights<<<dim3(256, 4), 256>>>(Wqkv, Wo, W1, W2);

    embed_kernel<<<ML, 64>>>(features, overlap_tag, poi_id, W_raw, b_raw,
                             pos_tab, type_tab, poi_tab, overlap_tab,
                             W_comb, b_comb, x, xh, zero);

    for (int l = 0; l < NL; l++) {
        gemm_qkv<<<dim3(3, ML / 128), 256>>>(
            xh, qkvT + l * 12288, bqkv + l * 192, qb, kb, vb);
        attn_kernel<<<BB * HH, 256, ATTN_SMEM>>>(qb, kb, vb, zero, attnh);
        wo_ffn_fused<<<ML / 128, 256, FFN_SMEM>>>(
            attnh, woT + l * 4096, bo + l * EE,
            ln1_s + l * EE, ln1_b + l * EE,
            w1T + l * DFF * 64, w2T + l * DFF * 64,
            b1 + l * DFF, b2 + l * EE,
            ln2_s + l * EE, ln2_b + l * EE,
            x, xh);
    }

    head_kernel<<<BB, VV * 3>>>(x, W_head, b_head, out);
}

// round 14
// speedup vs baseline: 1.1061x; 1.1061x over previous
#include <cuda_runtime.h>
#include <cuda_fp16.h>
#include <math.h>

#define BB 16
#define SS 16
#define VV 64
#define EE 64
#define HH 8
#define NL 4
#define DFF 2048
#define LL 1024
#define ML (BB*LL)
#define SPH 72   // smem row stride in halves (64 data + 8 pad) = 144 bytes

// ---------------- scratch ----------------
__device__ float g_x[ML * EE];            // fp32 residual stream
__device__ __half g_xh[ML * EE];          // fp16 copy of x
__device__ __half g_qh[ML * EE];          // Q fp16 pre-scaled [B][H][L][8]
__device__ __half g_kh[ML * EE];          // K fp16 [B][H][L][8]
__device__ __half g_vh[ML * EE];          // V fp16 [B][H][L][8]
__device__ __half g_attnh[ML * EE];       // attention output (fp16)
__device__ unsigned char g_zero[ML];

// pre-converted transposed fp16 weights ([n][k])
__device__ __align__(256) __half g_qkvT[NL * 192 * 64];
__device__ __align__(256) __half g_woT[NL * 64 * 64];
__device__ __align__(256) __half g_w1T[NL * DFF * 64];
__device__ __align__(256) __half g_w2T[NL * DFF * 64];

// ---------------- helpers ----------------
__device__ __forceinline__ unsigned pack2h(float a, float b) {
    __half2 h = __floats2half2_rn(a, b);
    return *(unsigned*)&h;
}
__device__ __forceinline__ void mma_f16(float* c, const unsigned* a, const unsigned* b) {
    asm volatile(
        "mma.sync.aligned.m16n8k16.row.col.f32.f16.f16.f32 "
        "{%0,%1,%2,%3}, {%4,%5,%6,%7}, {%8,%9}, {%0,%1,%2,%3};\n"
        : "+f"(c[0]), "+f"(c[1]), "+f"(c[2]), "+f"(c[3])
        : "r"(a[0]), "r"(a[1]), "r"(a[2]), "r"(a[3]), "r"(b[0]), "r"(b[1]));
}
__device__ __forceinline__ void ldsm_x4(unsigned* r, unsigned addr) {
    asm volatile("ldmatrix.sync.aligned.m8n8.x4.shared.b16 {%0,%1,%2,%3}, [%4];\n"
        : "=r"(r[0]), "=r"(r[1]), "=r"(r[2]), "=r"(r[3]) : "r"(addr));
}
__device__ __forceinline__ float warp_sum32(float v) {
#pragma unroll
    for (int o = 16; o > 0; o >>= 1) v += __shfl_xor_sync(0xffffffffu, v, o);
    return v;
}
#define CP_ASYNC16(dst, src) \
    asm volatile("cp.async.ca.shared.global [%0], [%1], 16;\n" :: "r"(dst), "l"(src))
#define CP_COMMIT() asm volatile("cp.async.commit_group;\n")
#define CP_WAIT1()  asm volatile("cp.async.wait_group 1;\n")
#define CP_WAIT0()  asm volatile("cp.async.wait_group 0;\n")

// ---------------- weight prep: coalesced tiled transpose ----------------
__global__ __launch_bounds__(256) void prep_weights(const float* __restrict__ Wqkv,
                                                    const float* __restrict__ Wo,
                                                    const float* __restrict__ W1,
                                                    const float* __restrict__ W2)
{
    __shared__ float s[64 * 65];
    int tid = threadIdx.x;
    int bx = blockIdx.x, which = blockIdx.y;

    if (which == 0) {
        if (bx >= NL * 6) return;
        int layer = bx / 6, n0 = (bx % 6) * 32;
        for (int i = tid; i < 2048; i += 256) {
            int k = i >> 5, n = i & 31;
            s[k * 33 + n] = Wqkv[(size_t)layer * 12288 + k * 192 + n0 + n];
        }
        __syncthreads();
        for (int i = tid; i < 2048; i += 256) {
            int n = i >> 6, k = i & 63;
            g_qkvT[(size_t)layer * 12288 + (n0 + n) * 64 + k] = __float2half_rn(s[k * 33 + n]);
        }
    } else if (which == 1) {
        if (bx >= NL * 2) return;
        int layer = bx / 2, n0 = (bx % 2) * 32;
        for (int i = tid; i < 2048; i += 256) {
            int k = i >> 5, n = i & 31;
            s[k * 33 + n] = Wo[(size_t)layer * 4096 + k * 64 + n0 + n];
        }
        __syncthreads();
        for (int i = tid; i < 2048; i += 256) {
            int n = i >> 6, k = i & 63;
            g_woT[(size_t)layer * 4096 + (n0 + n) * 64 + k] = __float2half_rn(s[k * 33 + n]);
        }
    } else if (which == 2) {
        if (bx >= NL * 64) return;
        int layer = bx / 64, n0 = (bx % 64) * 32;
        for (int i = tid; i < 2048; i += 256) {
            int k = i >> 5, n = i & 31;
            s[k * 33 + n] = W1[(size_t)layer * DFF * 64 + k * DFF + n0 + n];
        }
        __syncthreads();
        for (int i = tid; i < 2048; i += 256) {
            int n = i >> 6, k = i & 63;
            g_w1T[(size_t)layer * DFF * 64 + (n0 + n) * 64 + k] = __float2half_rn(s[k * 33 + n]);
        }
    } else {
        if (bx >= NL * 32) return;
        int layer = bx / 32, c = bx % 32;
        for (int i = tid; i < 4096; i += 256) {
            int kl = i >> 6, n = i & 63;
            s[kl * 65 + n] = W2[(size_t)layer * DFF * 64 + (c * 64 + kl) * 64 + n];
        }
        __syncthreads();
        for (int i = tid; i < 4096; i += 256) {
            int n = i >> 6, kl = i & 63;
            g_w2T[(size_t)layer * DFF * 64 + c * 4096 + n * 64 + kl] = __float2half_rn(s[kl * 65 + n]);
        }
    }
}

// ---------------- embed ----------------
__global__ void embed_kernel(const float* __restrict__ features,
                             const int* __restrict__ overlap_tag,
                             const int* __restrict__ poi_id,
                             const float* __restrict__ W_raw,
                             const float* __restrict__ b_raw,
                             const float* __restrict__ pos_tab,
                             const float* __restrict__ type_tab,
                             const float* __restrict__ poi_tab,
                             const float* __restrict__ overlap_tab,
                             const float* __restrict__ W_comb,
                             const float* __restrict__ b_comb,
                             float* __restrict__ x,
                             __half* __restrict__ xh,
                             unsigned char* __restrict__ zero_mask)
{
    int bl = blockIdx.x;
    int l  = bl & (LL - 1);
    int s  = l >> 6;
    int v  = l & 63;
    int tid = threadIdx.x;  // 64

    __shared__ float concat[80];
    const float* f = features + (size_t)bl * 3;
    float f0 = f[0], f1 = f[1], f2 = f[2];

    concat[tid] = f0 * W_raw[tid] + f1 * W_raw[64 + tid] + f2 * W_raw[128 + tid] + b_raw[tid];
    if (tid < 8) {
        int ov = overlap_tag[bl];
        concat[64 + tid] = (ov == 0) ? 0.0f : overlap_tab[ov * 8 + tid];
        int poi = poi_id[bl];
        concat[72 + tid] = (poi == 0) ? 0.0f : poi_tab[poi * 8 + tid];
    }
    if (tid == 0) zero_mask[bl] = (f0 + f1 + f2 == 0.0f) ? 1 : 0;
    __syncthreads();

    float acc = b_comb[tid];
#pragma unroll
    for (int j = 0; j < 80; j++) acc += concat[j] * W_comb[j * EE + tid];
    acc += pos_tab[s * EE + tid] + type_tab[v * EE + tid];
    x[(size_t)bl * EE + tid] = acc;
    xh[(size_t)bl * EE + tid] = __float2half_rn(acc);
}

// ---------------- QKV GEMM (fp16): Q pre-scaled fp16, K/V fp16, all permuted ----------------
__global__ __launch_bounds__(256) void gemm_qkv(const __half* __restrict__ Xh,
                                                const __half* __restrict__ WT,
                                                const float* __restrict__ bias,
                                                __half* __restrict__ Qo,
                                                __half* __restrict__ Ko,
                                                __half* __restrict__ Vo)
{
    __shared__ __align__(16) __half As[128 * SPH];
    __shared__ __align__(16) __half Ws[64 * SPH];

    int tid = threadIdx.x;
    int w = tid >> 5, lane = tid & 31;
    int wm = w >> 1, wn = w & 1;
    int rm = wm * 32, cn = wn * 32;
    int row0 = blockIdx.y * 128;
    int sel = blockIdx.x;
    int gr = lane >> 2, gc = (lane & 3) * 2;

    for (int i = tid; i < 1024; i += 256) {
        int r = i >> 3, seg = i & 7;
        *(uint4*)&As[r * SPH + seg * 8] = *(const uint4*)&Xh[(size_t)(row0 + r) * 64 + seg * 8];
    }
    const __half* src = WT + sel * 4096;
    for (int i = tid; i < 512; i += 256) {
        int n = i >> 3, seg = i & 7;
        *(uint4*)&Ws[n * SPH + seg * 8] = *(const uint4*)&src[n * 64 + seg * 8];
    }
    __syncthreads();

    float acc[2][4][4];
#pragma unroll
    for (int i = 0; i < 2; i++)
#pragma unroll
        for (int j = 0; j < 4; j++)
#pragma unroll
            for (int r = 0; r < 4; r++) acc[i][j][r] = 0.0f;

#pragma unroll
    for (int kt = 0; kt < 4; kt++) {
        int kk = kt * 16;
        unsigned a[2][4], b[4][2];
#pragma unroll
        for (int mi = 0; mi < 2; mi++) {
            int r = rm + mi * 16;
            a[mi][0] = *(unsigned*)&As[(r + gr) * SPH + kk + gc];
            a[mi][1] = *(unsigned*)&As[(r + gr + 8) * SPH + kk + gc];
            a[mi][2] = *(unsigned*)&As[(r + gr) * SPH + kk + gc + 8];
            a[mi][3] = *(unsigned*)&As[(r + gr + 8) * SPH + kk + gc + 8];
        }
#pragma unroll
        for (int ni = 0; ni < 4; ni++) {
            int n = cn + ni * 8 + gr;
            b[ni][0] = *(unsigned*)&Ws[n * SPH + kk + gc];
            b[ni][1] = *(unsigned*)&Ws[n * SPH + kk + gc + 8];
        }
#pragma unroll
        for (int mi = 0; mi < 2; mi++)
#pragma unroll
            for (int ni = 0; ni < 4; ni++)
                mma_f16(acc[mi][ni], a[mi], b[ni]);
    }

    int b = row0 >> 10;
    const float qscale = (sel == 0) ? 0.35355339059327373f : 1.0f;
    __half* outp = (sel == 0) ? Qo : ((sel == 1) ? Ko : Vo);
#pragma unroll
    for (int mi = 0; mi < 2; mi++) {
        int r0 = rm + mi * 16 + gr;
        int l0 = (row0 + r0) & (LL - 1);
#pragma unroll
        for (int ni = 0; ni < 4; ni++) {
            int loc = cn + ni * 8 + gc;
            int h = loc >> 3, d = loc & 7;
            float b0 = bias[sel * 64 + loc], b1v = bias[sel * 64 + loc + 1];
            size_t base = ((size_t)(b * 8 + h) * LL);
            *(unsigned*)&outp[(base + l0) * 8 + d] =
                pack2h((acc[mi][ni][0] + b0) * qscale, (acc[mi][ni][1] + b1v) * qscale);
            *(unsigned*)&outp[(base + l0 + 8) * 8 + d] =
                pack2h((acc[mi][ni][2] + b0) * qscale, (acc[mi][ni][3] + b1v) * qscale);
        }
    }
}

// ---------------- attention: fp16 K/V/Q, 2 adjacent queries/thread, 512 threads ----------------
#define ATTN_SMEM (32768 + 1024)

__device__ __forceinline__ float dot_h2(const __half2* q2, const uint4& kr) {
    const __half2* kh = (const __half2*)&kr;
    __half2 d = __hmul2(q2[0], kh[0]);
    d = __hfma2(q2[1], kh[1], d);
    d = __hfma2(q2[2], kh[2], d);
    d = __hfma2(q2[3], kh[3], d);
    return __low2float(d) + __high2float(d);
}

__global__ __launch_bounds__(512) void attn_kernel(const __half* __restrict__ Qg,
                                                   const __half* __restrict__ Kg,
                                                   const __half* __restrict__ Vg,
                                                   const unsigned char* __restrict__ zero_mask,
                                                   __half* __restrict__ out)
{
    extern __shared__ char smc[];
    __half* Ks = (__half*)smc;
    __half* Vs = (__half*)(smc + 16384);
    unsigned char* zs = (unsigned char*)(smc + 32768);

    int bh = blockIdx.x;
    int b = bh >> 3, h = bh & 7;
    int tid = threadIdx.x;                // 512
    size_t base = (size_t)bh * LL * 8;

    for (int i = tid; i < 1024; i += 512) {
        ((uint4*)Ks)[i] = ((const uint4*)(Kg + base))[i];
        ((uint4*)Vs)[i] = ((const uint4*)(Vg + base))[i];
    }
    for (int i = tid; i < 1024; i += 512) zs[i] = zero_mask[b * LL + i];
    __syncthreads();

    int q0 = tid * 2, q1 = q0 + 1;
    int tq = q0 >> 6;
    int vq0 = q0 & 63;

    uint4 qra = *(const uint4*)&Qg[base + q0 * 8];
    uint4 qrb = *(const uint4*)&Qg[base + q1 * 8];
    const __half2* qa2 = (const __half2*)&qra;
    const __half2* qb2 = (const __half2*)&qrb;

    float sA = 0.0f, sB = 0.0f;
    float accA[8] = {}, accB[8] = {};
    const __half2 hz = __floats2half2_rn(0.0f, 0.0f);

    int kb = tq << 6;
#pragma unroll
    for (int ch = 0; ch < 4; ch++) {
        __half2 aA[4] = {hz, hz, hz, hz};
        __half2 aB[4] = {hz, hz, hz, hz};
#pragma unroll
        for (int j = 0; j < 16; j++) {
            int k = kb + ch * 16 + j;
            uint4 kr = *(const uint4*)&Ks[k * 8];
            float dA = dot_h2(qa2, kr);
            float dB = dot_h2(qb2, kr);
            float wA = __expf(dA), wB = __expf(dB);
            if (zs[k]) { wA = 0.0f; wB = 0.0f; }
            sA += wA; sB += wB;
            __half2 wA2 = __float2half2_rn(wA);
            __half2 wB2 = __float2half2_rn(wB);
            uint4 vr = *(const uint4*)&Vs[k * 8];
            const __half2* vh = (const __half2*)&vr;
#pragma unroll
            for (int d = 0; d < 4; d++) {
                aA[d] = __hfma2(wA2, vh[d], aA[d]);
                aB[d] = __hfma2(wB2, vh[d], aB[d]);
            }
        }
#pragma unroll
        for (int d = 0; d < 4; d++) {
            float2 fa = __half22float2(aA[d]);
            float2 fb = __half22float2(aB[d]);
            accA[2 * d] += fa.x; accA[2 * d + 1] += fa.y;
            accB[2 * d] += fb.x; accB[2 * d + 1] += fb.y;
        }
    }

    {
        __half2 aA[4] = {hz, hz, hz, hz};
        __half2 aB[4] = {hz, hz, hz, hz};
#pragma unroll
        for (int t = 0; t < 16; t++) {
            if (t == tq) continue;
            int kA = (t << 6) + vq0;
            uint4 kr = *(const uint4*)&Ks[kA * 8];
            float dA = dot_h2(qa2, kr);
            float wA = __expf(dA);
            wA = zs[kA] ? 0.0f : wA;
            sA += wA;
            __half2 wA2 = __float2half2_rn(wA);
            uint4 vr = *(const uint4*)&Vs[kA * 8];
            const __half2* vh = (const __half2*)&vr;
#pragma unroll
            for (int d = 0; d < 4; d++) aA[d] = __hfma2(wA2, vh[d], aA[d]);

            int kB = kA + 1;
            uint4 kr2 = *(const uint4*)&Ks[kB * 8];
            float dB = dot_h2(qb2, kr2);
            float wB = __expf(dB);
            wB = zs[kB] ? 0.0f : wB;
            sB += wB;
            __half2 wB2 = __float2half2_rn(wB);
            uint4 vr2 = *(const uint4*)&Vs[kB * 8];
            const __half2* vh2 = (const __half2*)&vr2;
#pragma unroll
            for (int d = 0; d < 4; d++) aB[d] = __hfma2(wB2, vh2[d], aB[d]);
        }
#pragma unroll
        for (int d = 0; d < 4; d++) {
            float2 fa = __half22float2(aA[d]);
            float2 fb = __half22float2(aB[d]);
            accA[2 * d] += fa.x; accA[2 * d + 1] += fa.y;
            accB[2 * d] += fb.x; accB[2 * d + 1] += fb.y;
        }
    }

    float invA = 1.0f / sA, invB = 1.0f / sB;
    __half* oA = out + ((size_t)(b * LL + q0)) * EE + h * 8;
    uint4 pk;
    pk.x = pack2h(accA[0] * invA, accA[1] * invA);
    pk.y = pack2h(accA[2] * invA, accA[3] * invA);
    pk.z = pack2h(accA[4] * invA, accA[5] * invA);
    pk.w = pack2h(accA[6] * invA, accA[7] * invA);
    *(uint4*)oA = pk;
    __half* oB = out + ((size_t)(b * LL + q1)) * EE + h * 8;
    pk.x = pack2h(accB[0] * invB, accB[1] * invB);
    pk.y = pack2h(accB[2] * invB, accB[3] * invB);
    pk.z = pack2h(accB[4] * invB, accB[5] * invB);
    pk.w = pack2h(accB[6] * invB, accB[7] * invB);
    *(uint4*)oB = pk;
}

// ---------------- fused Wo+LN1+FFN+LN2 (fp16), 128 rows/block, 256 thr ----------------
// smem layout (bytes):
//   XS:   0      .. 18432   attnh tile, then post-LN1 x
//   HS0:  18432  .. 36864   Wo weights / o-proj / ffn h (even chunks)
//   HS1:  36864  .. 55296   ffn h (odd chunks)
//   WS:   55296  .. 92160   (2 stages * 18432)
//   buf:  aliases WS (128*65*4 = 33280 <= 36864), used after chunk loop
#define XS_OFF 0
#define HS_OFF 18432
#define HS_STRIDE 18432
#define WS_OFF 55296
#define WS_STRIDE 18432
#define FBUF_OFF 55296
#define FFN_SMEM 92160

__global__ __launch_bounds__(256) void wo_ffn_fused(const __half* __restrict__ attnh,
                                                    const __half* __restrict__ woT,
                                                    const float* __restrict__ bo,
                                                    const float* __restrict__ ln1_s,
                                                    const float* __restrict__ ln1_b,
                                                    const __half* __restrict__ w1T,
                                                    const __half* __restrict__ w2T,
                                                    const float* __restrict__ b1,
                                                    const float* __restrict__ b2,
                                                    const float* __restrict__ ln2_s,
                                                    const float* __restrict__ ln2_b,
                                                    float* __restrict__ x,
                                                    __half* __restrict__ xh)
{
    extern __shared__ __align__(16) char sm[];
    __half* XS = (__half*)(sm + XS_OFF);
    __half* HS0 = (__half*)(sm + HS_OFF);
    float* buf = (float*)(sm + FBUF_OFF);
    unsigned smem_base = (unsigned)__cvta_generic_to_shared(sm);

    int tid = threadIdx.x;
    int w = tid >> 5, lane = tid & 31;
    int wm = w >> 1, wn = w & 1;
    int rm = wm * 32, cn = wn * 32;
    int row0 = blockIdx.x * 128;
    int gr = lane >> 2, gc = (lane & 3) * 2;

    int a_row = (lane & 7) + ((lane >> 3) & 1) * 8;
    int a_col = (lane >> 4) * 8;
    int b_row = (lane & 7) + ((lane >> 4) & 1) * 8;
    int b_col = ((lane >> 3) & 1) * 8;
    unsigned aoff = (unsigned)(((rm + a_row) * SPH + a_col) * 2);
    unsigned boff = (unsigned)(((cn + b_row) * SPH + b_col) * 2);

    unsigned xs_b = smem_base + XS_OFF;
    unsigned hs_b = smem_base + HS_OFF;

    // group A: attnh tile -> XS + Wo weights -> HS0
    {
        int r = tid >> 1, sb = (tid & 1) * 4;
        const __half* src = attnh + (size_t)(row0 + r) * 64;
#pragma unroll
        for (int j = 0; j < 4; j++)
            CP_ASYNC16(xs_b + r * 144 + (sb + j) * 16, src + (sb + j) * 8);
        int n = tid >> 2, seg0 = (tid & 3) * 2;
        CP_ASYNC16(hs_b + n * 144 + seg0 * 16, woT + n * 64 + seg0 * 8);
        CP_ASYNC16(hs_b + n * 144 + (seg0 + 1) * 16, woT + n * 64 + (seg0 + 1) * 8);
    }
    CP_COMMIT();

    // group B: ffn chunk 0 -> WS stage 0
    int wr = tid >> 2, ws0 = (tid & 3) * 2;
    unsigned wdst = (unsigned)(wr * 144 + ws0 * 16);
    int wsrc = wr * 64 + ws0 * 8;
    {
        unsigned st = smem_base + WS_OFF;
        CP_ASYNC16(st + wdst, w1T + wsrc);
        CP_ASYNC16(st + wdst + 16, w1T + wsrc + 8);
        CP_ASYNC16(st + 9216 + wdst, w2T + wsrc);
        CP_ASYNC16(st + 9216 + wdst + 16, w2T + wsrc + 8);
    }
    CP_COMMIT();
    CP_WAIT1();           // group A done; group B may still be in flight
    __syncthreads();

    // ---- Wo GEMM ----
    float oacc[2][4][4];
#pragma unroll
    for (int i = 0; i < 2; i++)
#pragma unroll
        for (int j = 0; j < 4; j++)
#pragma unroll
            for (int r = 0; r < 4; r++) oacc[i][j][r] = 0.0f;

#pragma unroll
    for (int kt = 0; kt < 4; kt++) {
        unsigned kko = (unsigned)(kt * 32);
        unsigned a[2][4], bf[2][4];
        ldsm_x4(a[0], xs_b + aoff + kko);
        ldsm_x4(a[1], xs_b + aoff + 16 * 144 + kko);
        ldsm_x4(bf[0], hs_b + boff + kko);
        ldsm_x4(bf[1], hs_b + boff + 16 * 144 + kko);
#pragma unroll
        for (int mi = 0; mi < 2; mi++)
#pragma unroll
            for (int p = 0; p < 2; p++) {
                mma_f16(oacc[mi][p * 2],     a[mi], &bf[p][0]);
                mma_f16(oacc[mi][p * 2 + 1], a[mi], &bf[p][2]);
            }
    }
    __syncthreads();

#pragma unroll
    for (int mi = 0; mi < 2; mi++)
#pragma unroll
        for (int ni = 0; ni < 4; ni++) {
            int cl = cn + ni * 8 + gc;
            float bb0 = bo[cl], bb1 = bo[cl + 1];
            int r0 = rm + mi * 16 + gr;
            *(unsigned*)&HS0[r0 * SPH + cl] = pack2h(oacc[mi][ni][0] + bb0, oacc[mi][ni][1] + bb1);
            *(unsigned*)&HS0[(r0 + 8) * SPH + cl] = pack2h(oacc[mi][ni][2] + bb0, oacc[mi][ni][3] + bb1);
        }
    __syncthreads();

    // ---- LN1: x1 = LN(o + x_res); keep fp32 in regs, write fp16 to XS ----
    float xr0[16], xr1[16];
#pragma unroll
    for (int rr = 0; rr < 16; rr++) {
        int row = w * 16 + rr;
        size_t go = (size_t)(row0 + row) * 64;
        float y0 = __half2float(HS0[row * SPH + lane]) + x[go + lane];
        float y1 = __half2float(HS0[row * SPH + lane + 32]) + x[go + lane + 32];
        float mean = warp_sum32(y0 + y1) * (1.0f / 64.0f);
        float d0 = y0 - mean, d1 = y1 - mean;
        float var = warp_sum32(d0 * d0 + d1 * d1) * (1.0f / 64.0f);
        float inv = rsqrtf(var + 1e-5f);
        float o0 = d0 * inv * ln1_s[lane] + ln1_b[lane];
        float o1 = d1 * inv * ln1_s[lane + 32] + ln1_b[lane + 32];
        xr0[rr] = o0;
        xr1[rr] = o1;
        XS[row * SPH + lane] = __float2half_rn(o0);
        XS[row * SPH + lane + 32] = __float2half_rn(o1);
    }
    __syncthreads();

    // ---- FFN main loop: double-buffered H, 2 syncs/chunk ----
    float acc2[2][4][4];
#pragma unroll
    for (int i = 0; i < 2; i++)
#pragma unroll
        for (int j = 0; j < 4; j++)
#pragma unroll
            for (int r = 0; r < 4; r++) acc2[i][j][r] = 0.0f;

    for (int c = 0; c < 32; c++) {
        int s = c & 1;
        CP_WAIT0();
        __syncthreads();       // chunk c weights visible; all warps past GEMM2(c-1)

        if (c + 1 < 32) {      // prefetch chunk c+1 (safe: GEMM2(c-1) readers of WS[s^1] are done)
            unsigned st = smem_base + WS_OFF + (s ^ 1) * WS_STRIDE;
            int src = (c + 1) * 4096 + wsrc;
            CP_ASYNC16(st + wdst, w1T + src);
            CP_ASYNC16(st + wdst + 16, w1T + src + 8);
            CP_ASYNC16(st + 9216 + wdst, w2T + src);
            CP_ASYNC16(st + 9216 + wdst + 16, w2T + src + 8);
            CP_COMMIT();
        }

        unsigned w1_b = smem_base + WS_OFF + s * WS_STRIDE;
        unsigned w2_b = w1_b + 9216;
        unsigned hs_c = hs_b + s * HS_STRIDE;
        __half* HSc = (__half*)(sm + HS_OFF + s * HS_STRIDE);

        float hacc[2][4][4];
#pragma unroll
        for (int i = 0; i < 2; i++)
#pragma unroll
            for (int j = 0; j < 4; j++)
#pragma unroll
                for (int r = 0; r < 4; r++) hacc[i][j][r] = 0.0f;

#pragma unroll
        for (int kt = 0; kt < 4; kt++) {
            unsigned kko = (unsigned)(kt * 32);
            unsigned a[2][4], bf[2][4];
            ldsm_x4(a[0], xs_b + aoff + kko);
            ldsm_x4(a[1], xs_b + aoff + 16 * 144 + kko);
            ldsm_x4(bf[0], w1_b + boff + kko);
            ldsm_x4(bf[1], w1_b + boff + 16 * 144 + kko);
#pragma unroll
            for (int mi = 0; mi < 2; mi++)
#pragma unroll
                for (int p = 0; p < 2; p++) {
                    mma_f16(hacc[mi][p * 2],     a[mi], &bf[p][0]);
                    mma_f16(hacc[mi][p * 2 + 1], a[mi], &bf[p][2]);
                }
        }

#pragma unroll
        for (int mi = 0; mi < 2; mi++)
#pragma unroll
            for (int ni = 0; ni < 4; ni++) {
                int cl = cn + ni * 8 + gc;
                int cg = c * 64 + cl;
                float bb0 = b1[cg], bb1 = b1[cg + 1];
                float v0 = fmaxf(hacc[mi][ni][0] + bb0, 0.0f);
                float v1 = fmaxf(hacc[mi][ni][1] + bb1, 0.0f);
                float v2 = fmaxf(hacc[mi][ni][2] + bb0, 0.0f);
                float v3 = fmaxf(hacc[mi][ni][3] + bb1, 0.0f);
                *(unsigned*)&HSc[(rm + mi * 16 + gr) * SPH + cl] = pack2h(v0, v1);
                *(unsigned*)&HSc[(rm + mi * 16 + gr + 8) * SPH + cl] = pack2h(v2, v3);
            }
        __syncthreads();       // H visible

#pragma unroll
        for (int kt = 0; kt < 4; kt++) {
            unsigned kko = (unsigned)(kt * 32);
            unsigned a[2][4], bf[2][4];
            ldsm_x4(a[0], hs_c + aoff + kko);
            ldsm_x4(a[1], hs_c + aoff + 16 * 144 + kko);
            ldsm_x4(bf[0], w2_b + boff + kko);
            ldsm_x4(bf[1], w2_b + boff + 16 * 144 + kko);
#pragma unroll
            for (int mi = 0; mi < 2; mi++)
#pragma unroll
                for (int p = 0; p < 2; p++) {
                    mma_f16(acc2[mi][p * 2],     a[mi], &bf[p][0]);
                    mma_f16(acc2[mi][p * 2 + 1], a[mi], &bf[p][2]);
                }
        }
        // no trailing sync: next chunk's weight sync covers all hazards
    }
    __syncthreads();           // all GEMM2(31) reads of WS done before buf (aliases WS) is written

    // epilogue: + b2 -> buf, + residual(regs), LN2
#pragma unroll
    for (int mi = 0; mi < 2; mi++)
#pragma unroll
        for (int ni = 0; ni < 4; ni++) {
            int cc = cn + ni * 8 + gc;
            float b0 = b2[cc], b1v = b2[cc + 1];
            int r0 = rm + mi * 16 + gr;
            buf[r0 * 65 + cc] = acc2[mi][ni][0] + b0;
            buf[r0 * 65 + cc + 1] = acc2[mi][ni][1] + b1v;
            buf[(r0 + 8) * 65 + cc] = acc2[mi][ni][2] + b0;
            buf[(r0 + 8) * 65 + cc + 1] = acc2[mi][ni][3] + b1v;
        }
    __syncthreads();

#pragma unroll
    for (int rr = 0; rr < 16; rr++) {
        int row = w * 16 + rr;
        size_t go = (size_t)(row0 + row) * 64;
        float y0 = buf[row * 65 + lane] + xr0[rr];
        float y1 = buf[row * 65 + lane + 32] + xr1[rr];
        float mean = warp_sum32(y0 + y1) * (1.0f / 64.0f);
        float d0 = y0 - mean, d1 = y1 - mean;
        float var = warp_sum32(d0 * d0 + d1 * d1) * (1.0f / 64.0f);
        float inv = rsqrtf(var + 1e-5f);
        float o0 = d0 * inv * ln2_s[lane] + ln2_b[lane];
        float o1 = d1 * inv * ln2_s[lane + 32] + ln2_b[lane + 32];
        x[go + lane] = o0;
        x[go + lane + 32] = o1;
        xh[go + lane] = __float2half_rn(o0);
        xh[go + lane + 32] = __float2half_rn(o1);
    }
}

// ---------------- head ----------------
__global__ void head_kernel(const float* __restrict__ x,
                            const float* __restrict__ W_head,
                            const float* __restrict__ b_head,
                            float* __restrict__ out)
{
    int b = blockIdx.x;
    int tid = threadIdx.x;  // 192
    int v = tid / 3, c = tid % 3;
    const float* row = x + ((size_t)(b * LL + (SS - 1) * VV + v)) * EE;
    float acc = b_head[c];
#pragma unroll
    for (int e = 0; e < EE; e++) acc += row[e] * W_head[e * 3 + c];
    out[b * (VV * 3) + tid] = acc;
}

// ---------------- launch ----------------
extern "C" void kernel_launch(void* const* d_in, const int* in_sizes, int n_in,
                              void* d_out, int out_size)
{
    const float* features    = (const float*)d_in[0];
    const int*   overlap_tag = (const int*)d_in[1];
    const int*   poi_id      = (const int*)d_in[2];
    const float* W_raw       = (const float*)d_in[3];
    const float* b_raw       = (const float*)d_in[4];
    const float* pos_tab     = (const float*)d_in[5];
    const float* type_tab    = (const float*)d_in[6];
    const float* poi_tab     = (const float*)d_in[7];
    const float* overlap_tab = (const float*)d_in[8];
    const float* W_comb      = (const float*)d_in[9];
    const float* b_comb      = (const float*)d_in[10];
    const float* Wqkv        = (const float*)d_in[11];
    const float* bqkv        = (const float*)d_in[12];
    const float* Wo          = (const float*)d_in[13];
    const float* bo          = (const float*)d_in[14];
    const float* ln1_s       = (const float*)d_in[15];
    const float* ln1_b       = (const float*)d_in[16];
    const float* W1          = (const float*)d_in[17];
    const float* b1          = (const float*)d_in[18];
    const float* W2          = (const float*)d_in[19];
    const float* b2          = (const float*)d_in[20];
    const float* ln2_s       = (const float*)d_in[21];
    const float* ln2_b       = (const float*)d_in[22];
    const float* W_head      = (const float*)d_in[23];
    const float* b_head      = (const float*)d_in[24];
    float* out = (float*)d_out;

    float *x;
    __half *xh, *qb, *kb, *vb, *attnh, *qkvT, *woT, *w1T, *w2T;
    unsigned char* zero;
    cudaGetSymbolAddress((void**)&x,     g_x);
    cudaGetSymbolAddress((void**)&xh,    g_xh);
    cudaGetSymbolAddress((void**)&qb,    g_qh);
    cudaGetSymbolAddress((void**)&kb,    g_kh);
    cudaGetSymbolAddress((void**)&vb,    g_vh);
    cudaGetSymbolAddress((void**)&attnh, g_attnh);
    cudaGetSymbolAddress((void**)&zero,  g_zero);
    cudaGetSymbolAddress((void**)&qkvT,  g_qkvT);
    cudaGetSymbolAddress((void**)&woT,   g_woT);
    cudaGetSymbolAddress((void**)&w1T,   g_w1T);
    cudaGetSymbolAddress((void**)&w2T,   g_w2T);

    cudaFuncSetAttribute(attn_kernel, cudaFuncAttributeMaxDynamicSharedMemorySize, ATTN_SMEM);
    cudaFuncSetAttribute(wo_ffn_fused, cudaFuncAttributeMaxDynamicSharedMemorySize, FFN_SMEM);

    prep_weights<<<dim3(256, 4), 256>>>(Wqkv, Wo, W1, W2);

    embed_kernel<<<ML, 64>>>(features, overlap_tag, poi_id, W_raw, b_raw,
                             pos_tab, type_tab, poi_tab, overlap_tab,
                             W_comb, b_comb, x, xh, zero);

    for (int l = 0; l < NL; l++) {
        gemm_qkv<<<dim3(3, ML / 128), 256>>>(
            xh, qkvT + l * 12288, bqkv + l * 192, qb, kb, vb);
        attn_kernel<<<BB * HH, 512, ATTN_SMEM>>>(qb, kb, vb, zero, attnh);
        wo_ffn_fused<<<ML / 128, 256, FFN_SMEM>>>(
            attnh, woT + l * 4096, bo + l * EE,
            ln1_s + l * EE, ln1_b + l * EE,
            w1T + l * DFF * 64, w2T + l * DFF * 64,
            b1 + l * DFF, b2 + l * EE,
            ln2_s + l * EE, ln2_b + l * EE,
            x, xh);
    }

    head_kernel<<<BB, VV * 3>>>(x, W_head, b_head, out);
}

// round 15
// speedup vs baseline: 1.1647x; 1.0530x over previous
#include <cuda_runtime.h>
#include <cuda_fp16.h>
#include <math.h>

#define BB 16
#define SS 16
#define VV 64
#define EE 64
#define HH 8
#define NL 4
#define DFF 2048
#define LL 1024
#define ML (BB*LL)
#define SPH 72   // smem row stride in halves (64 data + 8 pad) = 144 bytes

// ---------------- scratch ----------------
__device__ float g_x[ML * EE];            // fp32 residual stream
__device__ __half g_xh[ML * EE];          // fp16 copy of x
__device__ __half g_qh[ML * EE];          // Q fp16 pre-scaled [B][H][L][8]
__device__ __half g_kh[ML * EE];          // K fp16 [B][H][L][8]
__device__ __half g_vh[ML * EE];          // V fp16 [B][H][L][8]
__device__ __half g_attnh[ML * EE];       // attention output (fp16)
__device__ unsigned char g_zero[ML];

// pre-converted transposed fp16 weights ([n][k])
__device__ __align__(256) __half g_qkvT[NL * 192 * 64];
__device__ __align__(256) __half g_woT[NL * 64 * 64];
__device__ __align__(256) __half g_w1T[NL * DFF * 64];
__device__ __align__(256) __half g_w2T[NL * DFF * 64];

// ---------------- helpers ----------------
__device__ __forceinline__ unsigned pack2h(float a, float b) {
    __half2 h = __floats2half2_rn(a, b);
    return *(unsigned*)&h;
}
__device__ __forceinline__ void mma_f16(float* c, const unsigned* a, const unsigned* b) {
    asm volatile(
        "mma.sync.aligned.m16n8k16.row.col.f32.f16.f16.f32 "
        "{%0,%1,%2,%3}, {%4,%5,%6,%7}, {%8,%9}, {%0,%1,%2,%3};\n"
        : "+f"(c[0]), "+f"(c[1]), "+f"(c[2]), "+f"(c[3])
        : "r"(a[0]), "r"(a[1]), "r"(a[2]), "r"(a[3]), "r"(b[0]), "r"(b[1]));
}
__device__ __forceinline__ void ldsm_x4(unsigned* r, unsigned addr) {
    asm volatile("ldmatrix.sync.aligned.m8n8.x4.shared.b16 {%0,%1,%2,%3}, [%4];\n"
        : "=r"(r[0]), "=r"(r[1]), "=r"(r[2]), "=r"(r[3]) : "r"(addr));
}
__device__ __forceinline__ float warp_sum32(float v) {
#pragma unroll
    for (int o = 16; o > 0; o >>= 1) v += __shfl_xor_sync(0xffffffffu, v, o);
    return v;
}
#define CP_ASYNC16(dst, src) \
    asm volatile("cp.async.ca.shared.global [%0], [%1], 16;\n" :: "r"(dst), "l"(src))
#define CP_COMMIT() asm volatile("cp.async.commit_group;\n")
#define CP_WAIT1()  asm volatile("cp.async.wait_group 1;\n")

// ---------------- weight prep: coalesced tiled transpose ----------------
__global__ __launch_bounds__(256) void prep_weights(const float* __restrict__ Wqkv,
                                                    const float* __restrict__ Wo,
                                                    const float* __restrict__ W1,
                                                    const float* __restrict__ W2)
{
    __shared__ float s[64 * 65];
    int tid = threadIdx.x;
    int bx = blockIdx.x, which = blockIdx.y;

    if (which == 0) {
        if (bx >= NL * 6) return;
        int layer = bx / 6, n0 = (bx % 6) * 32;
        for (int i = tid; i < 2048; i += 256) {
            int k = i >> 5, n = i & 31;
            s[k * 33 + n] = Wqkv[(size_t)layer * 12288 + k * 192 + n0 + n];
        }
        __syncthreads();
        for (int i = tid; i < 2048; i += 256) {
            int n = i >> 6, k = i & 63;
            g_qkvT[(size_t)layer * 12288 + (n0 + n) * 64 + k] = __float2half_rn(s[k * 33 + n]);
        }
    } else if (which == 1) {
        if (bx >= NL * 2) return;
        int layer = bx / 2, n0 = (bx % 2) * 32;
        for (int i = tid; i < 2048; i += 256) {
            int k = i >> 5, n = i & 31;
            s[k * 33 + n] = Wo[(size_t)layer * 4096 + k * 64 + n0 + n];
        }
        __syncthreads();
        for (int i = tid; i < 2048; i += 256) {
            int n = i >> 6, k = i & 63;
            g_woT[(size_t)layer * 4096 + (n0 + n) * 64 + k] = __float2half_rn(s[k * 33 + n]);
        }
    } else if (which == 2) {
        if (bx >= NL * 64) return;
        int layer = bx / 64, n0 = (bx % 64) * 32;
        for (int i = tid; i < 2048; i += 256) {
            int k = i >> 5, n = i & 31;
            s[k * 33 + n] = W1[(size_t)layer * DFF * 64 + k * DFF + n0 + n];
        }
        __syncthreads();
        for (int i = tid; i < 2048; i += 256) {
            int n = i >> 6, k = i & 63;
            g_w1T[(size_t)layer * DFF * 64 + (n0 + n) * 64 + k] = __float2half_rn(s[k * 33 + n]);
        }
    } else {
        if (bx >= NL * 32) return;
        int layer = bx / 32, c = bx % 32;
        for (int i = tid; i < 4096; i += 256) {
            int kl = i >> 6, n = i & 63;
            s[kl * 65 + n] = W2[(size_t)layer * DFF * 64 + (c * 64 + kl) * 64 + n];
        }
        __syncthreads();
        for (int i = tid; i < 4096; i += 256) {
            int n = i >> 6, kl = i & 63;
            g_w2T[(size_t)layer * DFF * 64 + c * 4096 + n * 64 + kl] = __float2half_rn(s[kl * 65 + n]);
        }
    }
}

// ---------------- embed ----------------
__global__ void embed_kernel(const float* __restrict__ features,
                             const int* __restrict__ overlap_tag,
                             const int* __restrict__ poi_id,
                             const float* __restrict__ W_raw,
                             const float* __restrict__ b_raw,
                             const float* __restrict__ pos_tab,
                             const float* __restrict__ type_tab,
                             const float* __restrict__ poi_tab,
                             const float* __restrict__ overlap_tab,
                             const float* __restrict__ W_comb,
                             const float* __restrict__ b_comb,
                             float* __restrict__ x,
                             __half* __restrict__ xh,
                             unsigned char* __restrict__ zero_mask)
{
    int bl = blockIdx.x;
    int l  = bl & (LL - 1);
    int s  = l >> 6;
    int v  = l & 63;
    int tid = threadIdx.x;  // 64

    __shared__ float concat[80];
    const float* f = features + (size_t)bl * 3;
    float f0 = f[0], f1 = f[1], f2 = f[2];

    concat[tid] = f0 * W_raw[tid] + f1 * W_raw[64 + tid] + f2 * W_raw[128 + tid] + b_raw[tid];
    if (tid < 8) {
        int ov = overlap_tag[bl];
        concat[64 + tid] = (ov == 0) ? 0.0f : overlap_tab[ov * 8 + tid];
        int poi = poi_id[bl];
        concat[72 + tid] = (poi == 0) ? 0.0f : poi_tab[poi * 8 + tid];
    }
    if (tid == 0) zero_mask[bl] = (f0 + f1 + f2 == 0.0f) ? 1 : 0;
    __syncthreads();

    float acc = b_comb[tid];
#pragma unroll
    for (int j = 0; j < 80; j++) acc += concat[j] * W_comb[j * EE + tid];
    acc += pos_tab[s * EE + tid] + type_tab[v * EE + tid];
    x[(size_t)bl * EE + tid] = acc;
    xh[(size_t)bl * EE + tid] = __float2half_rn(acc);
}

// ---------------- QKV GEMM (fp16): Q pre-scaled fp16, K/V fp16, all permuted ----------------
__global__ __launch_bounds__(256) void gemm_qkv(const __half* __restrict__ Xh,
                                                const __half* __restrict__ WT,
                                                const float* __restrict__ bias,
                                                __half* __restrict__ Qo,
                                                __half* __restrict__ Ko,
                                                __half* __restrict__ Vo)
{
    __shared__ __align__(16) __half As[128 * SPH];
    __shared__ __align__(16) __half Ws[64 * SPH];

    int tid = threadIdx.x;
    int w = tid >> 5, lane = tid & 31;
    int wm = w >> 1, wn = w & 1;
    int rm = wm * 32, cn = wn * 32;
    int row0 = blockIdx.y * 128;
    int sel = blockIdx.x;
    int gr = lane >> 2, gc = (lane & 3) * 2;

    for (int i = tid; i < 1024; i += 256) {
        int r = i >> 3, seg = i & 7;
        *(uint4*)&As[r * SPH + seg * 8] = *(const uint4*)&Xh[(size_t)(row0 + r) * 64 + seg * 8];
    }
    const __half* src = WT + sel * 4096;
    for (int i = tid; i < 512; i += 256) {
        int n = i >> 3, seg = i & 7;
        *(uint4*)&Ws[n * SPH + seg * 8] = *(const uint4*)&src[n * 64 + seg * 8];
    }
    __syncthreads();

    float acc[2][4][4];
#pragma unroll
    for (int i = 0; i < 2; i++)
#pragma unroll
        for (int j = 0; j < 4; j++)
#pragma unroll
            for (int r = 0; r < 4; r++) acc[i][j][r] = 0.0f;

#pragma unroll
    for (int kt = 0; kt < 4; kt++) {
        int kk = kt * 16;
        unsigned a[2][4], b[4][2];
#pragma unroll
        for (int mi = 0; mi < 2; mi++) {
            int r = rm + mi * 16;
            a[mi][0] = *(unsigned*)&As[(r + gr) * SPH + kk + gc];
            a[mi][1] = *(unsigned*)&As[(r + gr + 8) * SPH + kk + gc];
            a[mi][2] = *(unsigned*)&As[(r + gr) * SPH + kk + gc + 8];
            a[mi][3] = *(unsigned*)&As[(r + gr + 8) * SPH + kk + gc + 8];
        }
#pragma unroll
        for (int ni = 0; ni < 4; ni++) {
            int n = cn + ni * 8 + gr;
            b[ni][0] = *(unsigned*)&Ws[n * SPH + kk + gc];
            b[ni][1] = *(unsigned*)&Ws[n * SPH + kk + gc + 8];
        }
#pragma unroll
        for (int mi = 0; mi < 2; mi++)
#pragma unroll
            for (int ni = 0; ni < 4; ni++)
                mma_f16(acc[mi][ni], a[mi], b[ni]);
    }

    int b = row0 >> 10;
    const float qscale = (sel == 0) ? 0.35355339059327373f : 1.0f;
    __half* outp = (sel == 0) ? Qo : ((sel == 1) ? Ko : Vo);
#pragma unroll
    for (int mi = 0; mi < 2; mi++) {
        int r0 = rm + mi * 16 + gr;
        int l0 = (row0 + r0) & (LL - 1);
#pragma unroll
        for (int ni = 0; ni < 4; ni++) {
            int loc = cn + ni * 8 + gc;
            int h = loc >> 3, d = loc & 7;
            float b0 = bias[sel * 64 + loc], b1v = bias[sel * 64 + loc + 1];
            size_t base = ((size_t)(b * 8 + h) * LL);
            *(unsigned*)&outp[(base + l0) * 8 + d] =
                pack2h((acc[mi][ni][0] + b0) * qscale, (acc[mi][ni][1] + b1v) * qscale);
            *(unsigned*)&outp[(base + l0 + 8) * 8 + d] =
                pack2h((acc[mi][ni][2] + b0) * qscale, (acc[mi][ni][3] + b1v) * qscale);
        }
    }
}

// ---------------- attention: fp16 K/V/Q, 1 query/thread, 1024 threads ----------------
#define ATTN_SMEM (32768 + 1024)

__device__ __forceinline__ float dot_h2(const __half2* q2, const uint4& kr) {
    const __half2* kh = (const __half2*)&kr;
    __half2 d = __hmul2(q2[0], kh[0]);
    d = __hfma2(q2[1], kh[1], d);
    d = __hfma2(q2[2], kh[2], d);
    d = __hfma2(q2[3], kh[3], d);
    return __low2float(d) + __high2float(d);
}

__global__ __launch_bounds__(1024) void attn_kernel(const __half* __restrict__ Qg,
                                                    const __half* __restrict__ Kg,
                                                    const __half* __restrict__ Vg,
                                                    const unsigned char* __restrict__ zero_mask,
                                                    __half* __restrict__ out)
{
    extern __shared__ char smc[];
    __half* Ks = (__half*)smc;
    __half* Vs = (__half*)(smc + 16384);
    unsigned char* zs = (unsigned char*)(smc + 32768);

    int bh = blockIdx.x;                  // 128 blocks
    int b = bh >> 3, h = bh & 7;
    int tid = threadIdx.x;                // 1024
    size_t base = (size_t)bh * LL * 8;

    ((uint4*)Ks)[tid] = ((const uint4*)(Kg + base))[tid];
    ((uint4*)Vs)[tid] = ((const uint4*)(Vg + base))[tid];
    zs[tid] = zero_mask[b * LL + tid];
    __syncthreads();

    int q = tid;
    int tq = q >> 6;
    int vq = q & 63;

    uint4 qr = *(const uint4*)&Qg[base + q * 8];
    const __half2* q2 = (const __half2*)&qr;

    float sA = 0.0f;
    float acc[8] = {};
    const __half2 hz = __floats2half2_rn(0.0f, 0.0f);

    // block-diagonal part: 64 keys, 4 chunks of 16 with fp32 promotion
    int kb = tq << 6;
#pragma unroll
    for (int ch = 0; ch < 4; ch++) {
        __half2 a[4] = {hz, hz, hz, hz};
#pragma unroll
        for (int j = 0; j < 16; j++) {
            int k = kb + ch * 16 + j;
            uint4 kr = *(const uint4*)&Ks[k * 8];
            float dA = dot_h2(q2, kr);
            float wA = __expf(dA);
            wA = zs[k] ? 0.0f : wA;
            sA += wA;
            __half2 wA2 = __float2half2_rn(wA);
            uint4 vr = *(const uint4*)&Vs[k * 8];
            const __half2* vh = (const __half2*)&vr;
#pragma unroll
            for (int d = 0; d < 4; d++)
                a[d] = __hfma2(wA2, vh[d], a[d]);
        }
#pragma unroll
        for (int d = 0; d < 4; d++) {
            float2 fa = __half22float2(a[d]);
            acc[2 * d] += fa.x;
            acc[2 * d + 1] += fa.y;
        }
    }

    // same-type column: 15 keys
    {
        __half2 a[4] = {hz, hz, hz, hz};
#pragma unroll
        for (int t = 0; t < 16; t++) {
            if (t == tq) continue;
            int k = (t << 6) + vq;
            uint4 kr = *(const uint4*)&Ks[k * 8];
            float dA = dot_h2(q2, kr);
            float wA = __expf(dA);
            wA = zs[k] ? 0.0f : wA;
            sA += wA;
            __half2 wA2 = __float2half2_rn(wA);
            uint4 vr = *(const uint4*)&Vs[k * 8];
            const __half2* vh = (const __half2*)&vr;
#pragma unroll
            for (int d = 0; d < 4; d++) a[d] = __hfma2(wA2, vh[d], a[d]);
        }
#pragma unroll
        for (int d = 0; d < 4; d++) {
            float2 fa = __half22float2(a[d]);
            acc[2 * d] += fa.x;
            acc[2 * d + 1] += fa.y;
        }
    }

    float inv = 1.0f / sA;
    __half* o = out + ((size_t)(b * LL + q)) * EE + h * 8;
    uint4 pk;
    pk.x = pack2h(acc[0] * inv, acc[1] * inv);
    pk.y = pack2h(acc[2] * inv, acc[3] * inv);
    pk.z = pack2h(acc[4] * inv, acc[5] * inv);
    pk.w = pack2h(acc[6] * inv, acc[7] * inv);
    *(uint4*)o = pk;
}

// ---------------- fused Wo+LN1+FFN+LN2 (fp16), 128 rows/block, 256 thr (R12 version) ----------------
// smem layout (bytes):
//   XS:   0      .. 18432   attnh tile, then post-LN1 x
//   HS:   18432  .. 36864   Wo weights / o-proj / ffn h
//   WS:   36864  .. 73728   (2 stages * 18432)
//   buf:  aliases WS (128*65*4 = 33280), used after chunk loop
#define XS_OFF 0
#define HS_OFF 18432
#define WS_OFF 36864
#define WS_STRIDE 18432
#define FBUF_OFF 36864
#define FFN_SMEM 73728

__global__ __launch_bounds__(256) void wo_ffn_fused(const __half* __restrict__ attnh,
                                                    const __half* __restrict__ woT,
                                                    const float* __restrict__ bo,
                                                    const float* __restrict__ ln1_s,
                                                    const float* __restrict__ ln1_b,
                                                    const __half* __restrict__ w1T,
                                                    const __half* __restrict__ w2T,
                                                    const float* __restrict__ b1,
                                                    const float* __restrict__ b2,
                                                    const float* __restrict__ ln2_s,
                                                    const float* __restrict__ ln2_b,
                                                    float* __restrict__ x,
                                                    __half* __restrict__ xh)
{
    extern __shared__ __align__(16) char sm[];
    __half* XS = (__half*)(sm + XS_OFF);
    __half* HS = (__half*)(sm + HS_OFF);
    float* buf = (float*)(sm + FBUF_OFF);
    unsigned smem_base = (unsigned)__cvta_generic_to_shared(sm);

    int tid = threadIdx.x;
    int w = tid >> 5, lane = tid & 31;
    int wm = w >> 1, wn = w & 1;
    int rm = wm * 32, cn = wn * 32;
    int row0 = blockIdx.x * 128;
    int gr = lane >> 2, gc = (lane & 3) * 2;

    int a_row = (lane & 7) + ((lane >> 3) & 1) * 8;
    int a_col = (lane >> 4) * 8;
    int b_row = (lane & 7) + ((lane >> 4) & 1) * 8;
    int b_col = ((lane >> 3) & 1) * 8;
    unsigned aoff = (unsigned)(((rm + a_row) * SPH + a_col) * 2);
    unsigned boff = (unsigned)(((cn + b_row) * SPH + b_col) * 2);

    unsigned xs_b = smem_base + XS_OFF;
    unsigned hs_b = smem_base + HS_OFF;

    // group A: attnh tile -> XS + Wo weights -> HS
    {
        int r = tid >> 1, sb = (tid & 1) * 4;
        const __half* src = attnh + (size_t)(row0 + r) * 64;
#pragma unroll
        for (int j = 0; j < 4; j++)
            CP_ASYNC16(xs_b + r * 144 + (sb + j) * 16, src + (sb + j) * 8);
        int n = tid >> 2, seg0 = (tid & 3) * 2;
        CP_ASYNC16(hs_b + n * 144 + seg0 * 16, woT + n * 64 + seg0 * 8);
        CP_ASYNC16(hs_b + n * 144 + (seg0 + 1) * 16, woT + n * 64 + (seg0 + 1) * 8);
    }
    CP_COMMIT();

    // group B: ffn chunk 0 -> WS stage 0
    int wr = tid >> 2, ws0 = (tid & 3) * 2;
    unsigned wdst = (unsigned)(wr * 144 + ws0 * 16);
    int wsrc = wr * 64 + ws0 * 8;
    {
        unsigned st = smem_base + WS_OFF;
        CP_ASYNC16(st + wdst, w1T + wsrc);
        CP_ASYNC16(st + wdst + 16, w1T + wsrc + 8);
        CP_ASYNC16(st + 9216 + wdst, w2T + wsrc);
        CP_ASYNC16(st + 9216 + wdst + 16, w2T + wsrc + 8);
    }
    CP_COMMIT();
    CP_WAIT1();
    __syncthreads();

    // ---- Wo GEMM ----
    float oacc[2][4][4];
#pragma unroll
    for (int i = 0; i < 2; i++)
#pragma unroll
        for (int j = 0; j < 4; j++)
#pragma unroll
            for (int r = 0; r < 4; r++) oacc[i][j][r] = 0.0f;

#pragma unroll
    for (int kt = 0; kt < 4; kt++) {
        unsigned kko = (unsigned)(kt * 32);
        unsigned a[2][4], bf[2][4];
        ldsm_x4(a[0], xs_b + aoff + kko);
        ldsm_x4(a[1], xs_b + aoff + 16 * 144 + kko);
        ldsm_x4(bf[0], hs_b + boff + kko);
        ldsm_x4(bf[1], hs_b + boff + 16 * 144 + kko);
#pragma unroll
        for (int mi = 0; mi < 2; mi++)
#pragma unroll
            for (int p = 0; p < 2; p++) {
                mma_f16(oacc[mi][p * 2],     a[mi], &bf[p][0]);
                mma_f16(oacc[mi][p * 2 + 1], a[mi], &bf[p][2]);
            }
    }
    __syncthreads();

#pragma unroll
    for (int mi = 0; mi < 2; mi++)
#pragma unroll
        for (int ni = 0; ni < 4; ni++) {
            int cl = cn + ni * 8 + gc;
            float bb0 = bo[cl], bb1 = bo[cl + 1];
            int r0 = rm + mi * 16 + gr;
            *(unsigned*)&HS[r0 * SPH + cl] = pack2h(oacc[mi][ni][0] + bb0, oacc[mi][ni][1] + bb1);
            *(unsigned*)&HS[(r0 + 8) * SPH + cl] = pack2h(oacc[mi][ni][2] + bb0, oacc[mi][ni][3] + bb1);
        }
    __syncthreads();

    // ---- LN1: x1 = LN(o + x_res); keep fp32 in regs, write fp16 to XS ----
    float xr0[16], xr1[16];
#pragma unroll
    for (int rr = 0; rr < 16; rr++) {
        int row = w * 16 + rr;
        size_t go = (size_t)(row0 + row) * 64;
        float y0 = __half2float(HS[row * SPH + lane]) + x[go + lane];
        float y1 = __half2float(HS[row * SPH + lane + 32]) + x[go + lane + 32];
        float mean = warp_sum32(y0 + y1) * (1.0f / 64.0f);
        float d0 = y0 - mean, d1 = y1 - mean;
        float var = warp_sum32(d0 * d0 + d1 * d1) * (1.0f / 64.0f);
        float inv = rsqrtf(var + 1e-5f);
        float o0 = d0 * inv * ln1_s[lane] + ln1_b[lane];
        float o1 = d1 * inv * ln1_s[lane + 32] + ln1_b[lane + 32];
        xr0[rr] = o0;
        xr1[rr] = o1;
        XS[row * SPH + lane] = __float2half_rn(o0);
        XS[row * SPH + lane + 32] = __float2half_rn(o1);
    }
    __syncthreads();

    // ---- FFN main loop (R12 3-sync version) ----
    float acc2[2][4][4];
#pragma unroll
    for (int i = 0; i < 2; i++)
#pragma unroll
        for (int j = 0; j < 4; j++)
#pragma unroll
            for (int r = 0; r < 4; r++) acc2[i][j][r] = 0.0f;

    for (int c = 0; c < 32; c++) {
        int s = c & 1;
        if (c + 1 < 32) {
            unsigned st = smem_base + WS_OFF + (s ^ 1) * WS_STRIDE;
            int src = (c + 1) * 4096 + wsrc;
            CP_ASYNC16(st + wdst, w1T + src);
            CP_ASYNC16(st + wdst + 16, w1T + src + 8);
            CP_ASYNC16(st + 9216 + wdst, w2T + src);
            CP_ASYNC16(st + 9216 + wdst + 16, w2T + src + 8);
        }
        CP_COMMIT();
        CP_WAIT1();
        __syncthreads();

        unsigned w1_b = smem_base + WS_OFF + s * WS_STRIDE;
        unsigned w2_b = w1_b + 9216;

        float hacc[2][4][4];
#pragma unroll
        for (int i = 0; i < 2; i++)
#pragma unroll
            for (int j = 0; j < 4; j++)
#pragma unroll
                for (int r = 0; r < 4; r++) hacc[i][j][r] = 0.0f;

#pragma unroll
        for (int kt = 0; kt < 4; kt++) {
            unsigned kko = (unsigned)(kt * 32);
            unsigned a[2][4], bf[2][4];
            ldsm_x4(a[0], xs_b + aoff + kko);
            ldsm_x4(a[1], xs_b + aoff + 16 * 144 + kko);
            ldsm_x4(bf[0], w1_b + boff + kko);
            ldsm_x4(bf[1], w1_b + boff + 16 * 144 + kko);
#pragma unroll
            for (int mi = 0; mi < 2; mi++)
#pragma unroll
                for (int p = 0; p < 2; p++) {
                    mma_f16(hacc[mi][p * 2],     a[mi], &bf[p][0]);
                    mma_f16(hacc[mi][p * 2 + 1], a[mi], &bf[p][2]);
                }
        }

#pragma unroll
        for (int mi = 0; mi < 2; mi++)
#pragma unroll
            for (int ni = 0; ni < 4; ni++) {
                int cl = cn + ni * 8 + gc;
                int cg = c * 64 + cl;
                float bb0 = b1[cg], bb1 = b1[cg + 1];
                float v0 = fmaxf(hacc[mi][ni][0] + bb0, 0.0f);
                float v1 = fmaxf(hacc[mi][ni][1] + bb1, 0.0f);
                float v2 = fmaxf(hacc[mi][ni][2] + bb0, 0.0f);
                float v3 = fmaxf(hacc[mi][ni][3] + bb1, 0.0f);
                *(unsigned*)&HS[(rm + mi * 16 + gr) * SPH + cl] = pack2h(v0, v1);
                *(unsigned*)&HS[(rm + mi * 16 + gr + 8) * SPH + cl] = pack2h(v2, v3);
            }
        __syncthreads();

#pragma unroll
        for (int kt = 0; kt < 4; kt++) {
            unsigned kko = (unsigned)(kt * 32);
            unsigned a[2][4], bf[2][4];
            ldsm_x4(a[0], hs_b + aoff + kko);
            ldsm_x4(a[1], hs_b + aoff + 16 * 144 + kko);
            ldsm_x4(bf[0], w2_b + boff + kko);
            ldsm_x4(bf[1], w2_b + boff + 16 * 144 + kko);
#pragma unroll
            for (int mi = 0; mi < 2; mi++)
#pragma unroll
                for (int p = 0; p < 2; p++) {
                    mma_f16(acc2[mi][p * 2],     a[mi], &bf[p][0]);
                    mma_f16(acc2[mi][p * 2 + 1], a[mi], &bf[p][2]);
                }
        }
        __syncthreads();
    }

    // epilogue: + b2 -> buf, + residual(regs), LN2
#pragma unroll
    for (int mi = 0; mi < 2; mi++)
#pragma unroll
        for (int ni = 0; ni < 4; ni++) {
            int cc = cn + ni * 8 + gc;
            float b0 = b2[cc], b1v = b2[cc + 1];
            int r0 = rm + mi * 16 + gr;
            buf[r0 * 65 + cc] = acc2[mi][ni][0] + b0;
            buf[r0 * 65 + cc + 1] = acc2[mi][ni][1] + b1v;
            buf[(r0 + 8) * 65 + cc] = acc2[mi][ni][2] + b0;
            buf[(r0 + 8) * 65 + cc + 1] = acc2[mi][ni][3] + b1v;
        }
    __syncthreads();

#pragma unroll
    for (int rr = 0; rr < 16; rr++) {
        int row = w * 16 + rr;
        size_t go = (size_t)(row0 + row) * 64;
        float y0 = buf[row * 65 + lane] + xr0[rr];
        float y1 = buf[row * 65 + lane + 32] + xr1[rr];
        float mean = warp_sum32(y0 + y1) * (1.0f / 64.0f);
        float d0 = y0 - mean, d1 = y1 - mean;
        float var = warp_sum32(d0 * d0 + d1 * d1) * (1.0f / 64.0f);
        float inv = rsqrtf(var + 1e-5f);
        float o0 = d0 * inv * ln2_s[lane] + ln2_b[lane];
        float o1 = d1 * inv * ln2_s[lane + 32] + ln2_b[lane + 32];
        x[go + lane] = o0;
        x[go + lane + 32] = o1;
        xh[go + lane] = __float2half_rn(o0);
        xh[go + lane + 32] = __float2half_rn(o1);
    }
}

// ---------------- head ----------------
__global__ void head_kernel(const float* __restrict__ x,
                            const float* __restrict__ W_head,
                            const float* __restrict__ b_head,
                            float* __restrict__ out)
{
    int b = blockIdx.x;
    int tid = threadIdx.x;  // 192
    int v = tid / 3, c = tid % 3;
    const float* row = x + ((size_t)(b * LL + (SS - 1) * VV + v)) * EE;
    float acc = b_head[c];
#pragma unroll
    for (int e = 0; e < EE; e++) acc += row[e] * W_head[e * 3 + c];
    out[b * (VV * 3) + tid] = acc;
}

// ---------------- launch ----------------
extern "C" void kernel_launch(void* const* d_in, const int* in_sizes, int n_in,
                              void* d_out, int out_size)
{
    const float* features    = (const float*)d_in[0];
    const int*   overlap_tag = (const int*)d_in[1];
    const int*   poi_id      = (const int*)d_in[2];
    const float* W_raw       = (const float*)d_in[3];
    const float* b_raw       = (const float*)d_in[4];
    const float* pos_tab     = (const float*)d_in[5];
    const float* type_tab    = (const float*)d_in[6];
    const float* poi_tab     = (const float*)d_in[7];
    const float* overlap_tab = (const float*)d_in[8];
    const float* W_comb      = (const float*)d_in[9];
    const float* b_comb      = (const float*)d_in[10];
    const float* Wqkv        = (const float*)d_in[11];
    const float* bqkv        = (const float*)d_in[12];
    const float* Wo          = (const float*)d_in[13];
    const float* bo          = (const float*)d_in[14];
    const float* ln1_s       = (const float*)d_in[15];
    const float* ln1_b       = (const float*)d_in[16];
    const float* W1          = (const float*)d_in[17];
    const float* b1          = (const float*)d_in[18];
    const float* W2          = (const float*)d_in[19];
    const float* b2          = (const float*)d_in[20];
    const float* ln2_s       = (const float*)d_in[21];
    const float* ln2_b       = (const float*)d_in[22];
    const float* W_head      = (const float*)d_in[23];
    const float* b_head      = (const float*)d_in[24];
    float* out = (float*)d_out;

    float *x;
    __half *xh, *qb, *kb, *vb, *attnh, *qkvT, *woT, *w1T, *w2T;
    unsigned char* zero;
    cudaGetSymbolAddress((void**)&x,     g_x);
    cudaGetSymbolAddress((void**)&xh,    g_xh);
    cudaGetSymbolAddress((void**)&qb,    g_qh);
    cudaGetSymbolAddress((void**)&kb,    g_kh);
    cudaGetSymbolAddress((void**)&vb,    g_vh);
    cudaGetSymbolAddress((void**)&attnh, g_attnh);
    cudaGetSymbolAddress((void**)&zero,  g_zero);
    cudaGetSymbolAddress((void**)&qkvT,  g_qkvT);
    cudaGetSymbolAddress((void**)&woT,   g_woT);
    cudaGetSymbolAddress((void**)&w1T,   g_w1T);
    cudaGetSymbolAddress((void**)&w2T,   g_w2T);

    cudaFuncSetAttribute(attn_kernel, cudaFuncAttributeMaxDynamicSharedMemorySize, ATTN_SMEM);
    cudaFuncSetAttribute(wo_ffn_fused, cudaFuncAttributeMaxDynamicSharedMemorySize, FFN_SMEM);

    prep_weights<<<dim3(256, 4), 256>>>(Wqkv, Wo, W1, W2);

    embed_kernel<<<ML, 64>>>(features, overlap_tag, poi_id, W_raw, b_raw,
                             pos_tab, type_tab, poi_tab, overlap_tab,
                             W_comb, b_comb, x, xh, zero);

    for (int l = 0; l < NL; l++) {
        gemm_qkv<<<dim3(3, ML / 128), 256>>>(
            xh, qkvT + l * 12288, bqkv + l * 192, qb, kb, vb);
        attn_kernel<<<BB * HH, 1024, ATTN_SMEM>>>(qb, kb, vb, zero, attnh);
        wo_ffn_fused<<<ML / 128, 256, FFN_SMEM>>>(
            attnh, woT + l * 4096, bo + l * EE,
            ln1_s + l * EE, ln1_b + l * EE,
            w1T + l * DFF * 64, w2T + l * DFF * 64,
            b1 + l * DFF, b2 + l * EE,
            ln2_s + l * EE, ln2_b + l * EE,
            x, xh);
    }

    head_kernel<<<BB, VV * 3>>>(x, W_head, b_head, out);
}

// round 16
// speedup vs baseline: 1.1824x; 1.0152x over previous
#include <cuda_runtime.h>
#include <cuda_fp16.h>
#include <math.h>

#define BB 16
#define SS 16
#define VV 64
#define EE 64
#define HH 8
#define NL 4
#define DFF 2048
#define LL 1024
#define ML (BB*LL)
#define SPH 72   // smem row stride in halves (64 data + 8 pad) = 144 bytes

// ---------------- scratch ----------------
__device__ float g_x[ML * EE];            // fp32 residual stream
__device__ __half g_xh[ML * EE];          // fp16 copy of x
__device__ __half g_attnh[ML * EE];       // attention output (fp16)
__device__ unsigned char g_zero[ML];

// pre-converted transposed fp16 weights ([n][k])
__device__ __align__(256) __half g_qkvT[NL * 192 * 64];
__device__ __align__(256) __half g_woT[NL * 64 * 64];
__device__ __align__(256) __half g_w1T[NL * DFF * 64];
__device__ __align__(256) __half g_w2T[NL * DFF * 64];

// ---------------- helpers ----------------
__device__ __forceinline__ unsigned pack2h(float a, float b) {
    __half2 h = __floats2half2_rn(a, b);
    return *(unsigned*)&h;
}
__device__ __forceinline__ void mma_f16(float* c, const unsigned* a, const unsigned* b) {
    asm volatile(
        "mma.sync.aligned.m16n8k16.row.col.f32.f16.f16.f32 "
        "{%0,%1,%2,%3}, {%4,%5,%6,%7}, {%8,%9}, {%0,%1,%2,%3};\n"
        : "+f"(c[0]), "+f"(c[1]), "+f"(c[2]), "+f"(c[3])
        : "r"(a[0]), "r"(a[1]), "r"(a[2]), "r"(a[3]), "r"(b[0]), "r"(b[1]));
}
__device__ __forceinline__ void ldsm_x4(unsigned* r, unsigned addr) {
    asm volatile("ldmatrix.sync.aligned.m8n8.x4.shared.b16 {%0,%1,%2,%3}, [%4];\n"
        : "=r"(r[0]), "=r"(r[1]), "=r"(r[2]), "=r"(r[3]) : "r"(addr));
}
__device__ __forceinline__ float warp_sum32(float v) {
#pragma unroll
    for (int o = 16; o > 0; o >>= 1) v += __shfl_xor_sync(0xffffffffu, v, o);
    return v;
}
#define CP_ASYNC16(dst, src) \
    asm volatile("cp.async.ca.shared.global [%0], [%1], 16;\n" :: "r"(dst), "l"(src))
#define CP_COMMIT() asm volatile("cp.async.commit_group;\n")
#define CP_WAIT1()  asm volatile("cp.async.wait_group 1;\n")
#define CP_WAIT0()  asm volatile("cp.async.wait_group 0;\n")

// ---------------- weight prep: coalesced tiled transpose ----------------
__global__ __launch_bounds__(256) void prep_weights(const float* __restrict__ Wqkv,
                                                    const float* __restrict__ Wo,
                                                    const float* __restrict__ W1,
                                                    const float* __restrict__ W2)
{
    __shared__ float s[64 * 65];
    int tid = threadIdx.x;
    int bx = blockIdx.x, which = blockIdx.y;

    if (which == 0) {
        if (bx >= NL * 6) return;
        int layer = bx / 6, n0 = (bx % 6) * 32;
        for (int i = tid; i < 2048; i += 256) {
            int k = i >> 5, n = i & 31;
            s[k * 33 + n] = Wqkv[(size_t)layer * 12288 + k * 192 + n0 + n];
        }
        __syncthreads();
        for (int i = tid; i < 2048; i += 256) {
            int n = i >> 6, k = i & 63;
            g_qkvT[(size_t)layer * 12288 + (n0 + n) * 64 + k] = __float2half_rn(s[k * 33 + n]);
        }
    } else if (which == 1) {
        if (bx >= NL * 2) return;
        int layer = bx / 2, n0 = (bx % 2) * 32;
        for (int i = tid; i < 2048; i += 256) {
            int k = i >> 5, n = i & 31;
            s[k * 33 + n] = Wo[(size_t)layer * 4096 + k * 64 + n0 + n];
        }
        __syncthreads();
        for (int i = tid; i < 2048; i += 256) {
            int n = i >> 6, k = i & 63;
            g_woT[(size_t)layer * 4096 + (n0 + n) * 64 + k] = __float2half_rn(s[k * 33 + n]);
        }
    } else if (which == 2) {
        if (bx >= NL * 64) return;
        int layer = bx / 64, n0 = (bx % 64) * 32;
        for (int i = tid; i < 2048; i += 256) {
            int k = i >> 5, n = i & 31;
            s[k * 33 + n] = W1[(size_t)layer * DFF * 64 + k * DFF + n0 + n];
        }
        __syncthreads();
        for (int i = tid; i < 2048; i += 256) {
            int n = i >> 6, k = i & 63;
            g_w1T[(size_t)layer * DFF * 64 + (n0 + n) * 64 + k] = __float2half_rn(s[k * 33 + n]);
        }
    } else {
        if (bx >= NL * 32) return;
        int layer = bx / 32, c = bx % 32;
        for (int i = tid; i < 4096; i += 256) {
            int kl = i >> 6, n = i & 63;
            s[kl * 65 + n] = W2[(size_t)layer * DFF * 64 + (c * 64 + kl) * 64 + n];
        }
        __syncthreads();
        for (int i = tid; i < 4096; i += 256) {
            int n = i >> 6, kl = i & 63;
            g_w2T[(size_t)layer * DFF * 64 + c * 4096 + n * 64 + kl] = __float2half_rn(s[kl * 65 + n]);
        }
    }
}

// ---------------- embed ----------------
__global__ void embed_kernel(const float* __restrict__ features,
                             const int* __restrict__ overlap_tag,
                             const int* __restrict__ poi_id,
                             const float* __restrict__ W_raw,
                             const float* __restrict__ b_raw,
                             const float* __restrict__ pos_tab,
                             const float* __restrict__ type_tab,
                             const float* __restrict__ poi_tab,
                             const float* __restrict__ overlap_tab,
                             const float* __restrict__ W_comb,
                             const float* __restrict__ b_comb,
                             float* __restrict__ x,
                             __half* __restrict__ xh,
                             unsigned char* __restrict__ zero_mask)
{
    int bl = blockIdx.x;
    int l  = bl & (LL - 1);
    int s  = l >> 6;
    int v  = l & 63;
    int tid = threadIdx.x;  // 64

    __shared__ float concat[80];
    const float* f = features + (size_t)bl * 3;
    float f0 = f[0], f1 = f[1], f2 = f[2];

    concat[tid] = f0 * W_raw[tid] + f1 * W_raw[64 + tid] + f2 * W_raw[128 + tid] + b_raw[tid];
    if (tid < 8) {
        int ov = overlap_tag[bl];
        concat[64 + tid] = (ov == 0) ? 0.0f : overlap_tab[ov * 8 + tid];
        int poi = poi_id[bl];
        concat[72 + tid] = (poi == 0) ? 0.0f : poi_tab[poi * 8 + tid];
    }
    if (tid == 0) zero_mask[bl] = (f0 + f1 + f2 == 0.0f) ? 1 : 0;
    __syncthreads();

    float acc = b_comb[tid];
#pragma unroll
    for (int j = 0; j < 80; j++) acc += concat[j] * W_comb[j * EE + tid];
    acc += pos_tab[s * EE + tid] + type_tab[v * EE + tid];
    x[(size_t)bl * EE + tid] = acc;
    xh[(size_t)bl * EE + tid] = __float2half_rn(acc);
}

// ---------------- fused QKV + attention: one block per (b,h), 1024 threads ----------------
// smem (bytes):
//   XH: 0      .. 147456   (1024 rows * 144B, SPH stride)
//   WQ: 147456 .. 152064   (32 rows * 144B; 24 used: [Q|K|V] x 8 cols of head h)
//   QS: 152064 .. 168448   (1024 x 8 fp16, pre-scaled)
//   KS: 168448 .. 184832
//   VS: 184832 .. 201216
//   ZS: 201216 .. 202240
#define XH_OFF 0
#define WQ_OFF 147456
#define QS_OFF 152064
#define KS_OFF 168448
#define VS_OFF 184832
#define ZS_OFF 201216
#define ATTN_SMEM 202240

__device__ __forceinline__ float dot_h2(const __half2* q2, const uint4& kr) {
    const __half2* kh = (const __half2*)&kr;
    __half2 d = __hmul2(q2[0], kh[0]);
    d = __hfma2(q2[1], kh[1], d);
    d = __hfma2(q2[2], kh[2], d);
    d = __hfma2(q2[3], kh[3], d);
    return __low2float(d) + __high2float(d);
}

__global__ __launch_bounds__(1024) void attn_kernel(const __half* __restrict__ xh,
                                                    const __half* __restrict__ qkvT,
                                                    const float* __restrict__ bqkv,
                                                    const unsigned char* __restrict__ zero_mask,
                                                    __half* __restrict__ out)
{
    extern __shared__ char smc[];
    __half* XH = (__half*)(smc + XH_OFF);
    __half* QS = (__half*)(smc + QS_OFF);
    __half* KS = (__half*)(smc + KS_OFF);
    __half* VS = (__half*)(smc + VS_OFF);
    unsigned char* zs = (unsigned char*)(smc + ZS_OFF);
    unsigned sb = (unsigned)__cvta_generic_to_shared(smc);

    int bh = blockIdx.x;                  // 128 blocks
    int b = bh >> 3, h = bh & 7;
    int tid = threadIdx.x;                // 1024
    int w = tid >> 5, lane = tid & 31;

    // ---- load xh[b] tile (1024x64 -> SPH stride) via cp.async ----
    const __half* xsrc = xh + (size_t)b * LL * 64;
#pragma unroll
    for (int it = 0; it < 8; it++) {
        int i = tid + it * 1024;
        int r = i >> 3, seg = i & 7;
        CP_ASYNC16(sb + XH_OFF + r * 144 + seg * 16, xsrc + r * 64 + seg * 8);
    }
    // ---- load 24 weight rows (Q/K/V cols of head h) ----
    if (tid < 192) {
        int n = tid >> 3, seg = tid & 7;
        int ni = n >> 3;
        int gn = ni * 64 + h * 8 + (n & 7);
        CP_ASYNC16(sb + WQ_OFF + n * 144 + seg * 16, qkvT + gn * 64 + seg * 8);
    }
    zs[tid] = zero_mask[b * LL + tid];
    CP_COMMIT();
    CP_WAIT0();
    __syncthreads();

    // ---- QKV MMA phase: warp w handles rows [w*32, w*32+32) ----
    {
        int rm = w * 32;
        int gr = lane >> 2, gc = (lane & 3) * 2;
        float acc[2][3][4];
#pragma unroll
        for (int mi = 0; mi < 2; mi++)
#pragma unroll
            for (int ni = 0; ni < 3; ni++)
#pragma unroll
                for (int r = 0; r < 4; r++) acc[mi][ni][r] = 0.0f;

        const __half* WQ = (const __half*)(smc + WQ_OFF);
#pragma unroll
        for (int kt = 0; kt < 4; kt++) {
            int kk = kt * 16;
            unsigned a[2][4], bf[3][2];
#pragma unroll
            for (int mi = 0; mi < 2; mi++) {
                int r = rm + mi * 16;
                a[mi][0] = *(unsigned*)&XH[(r + gr) * SPH + kk + gc];
                a[mi][1] = *(unsigned*)&XH[(r + gr + 8) * SPH + kk + gc];
                a[mi][2] = *(unsigned*)&XH[(r + gr) * SPH + kk + gc + 8];
                a[mi][3] = *(unsigned*)&XH[(r + gr + 8) * SPH + kk + gc + 8];
            }
#pragma unroll
            for (int ni = 0; ni < 3; ni++) {
                int n = ni * 8 + gr;
                bf[ni][0] = *(unsigned*)&WQ[n * SPH + kk + gc];
                bf[ni][1] = *(unsigned*)&WQ[n * SPH + kk + gc + 8];
            }
#pragma unroll
            for (int mi = 0; mi < 2; mi++)
#pragma unroll
                for (int ni = 0; ni < 3; ni++)
                    mma_f16(acc[mi][ni], a[mi], bf[ni]);
        }

        const float qsc = 0.35355339059327373f;
#pragma unroll
        for (int mi = 0; mi < 2; mi++) {
            int r0 = rm + mi * 16 + gr;
#pragma unroll
            for (int ni = 0; ni < 3; ni++) {
                __half* op = (ni == 0) ? QS : ((ni == 1) ? KS : VS);
                float sc = (ni == 0) ? qsc : 1.0f;
                float b0 = bqkv[ni * 64 + h * 8 + gc];
                float b1 = bqkv[ni * 64 + h * 8 + gc + 1];
                *(unsigned*)&op[r0 * 8 + gc] =
                    pack2h((acc[mi][ni][0] + b0) * sc, (acc[mi][ni][1] + b1) * sc);
                *(unsigned*)&op[(r0 + 8) * 8 + gc] =
                    pack2h((acc[mi][ni][2] + b0) * sc, (acc[mi][ni][3] + b1) * sc);
            }
        }
    }
    __syncthreads();

    // ---- attention: 1 query/thread ----
    int q = tid;
    int tq = q >> 6;
    int vq = q & 63;

    uint4 qr = *(const uint4*)&QS[q * 8];
    const __half2* q2 = (const __half2*)&qr;

    float sA = 0.0f;
    float acc[8] = {};
    const __half2 hz = __floats2half2_rn(0.0f, 0.0f);

    // block-diagonal part: 64 keys, 4 chunks of 16 with fp32 promotion
    int kb = tq << 6;
#pragma unroll
    for (int ch = 0; ch < 4; ch++) {
        __half2 a[4] = {hz, hz, hz, hz};
#pragma unroll
        for (int j = 0; j < 16; j++) {
            int k = kb + ch * 16 + j;
            uint4 kr = *(const uint4*)&KS[k * 8];
            float dA = dot_h2(q2, kr);
            float wA = __expf(dA);
            wA = zs[k] ? 0.0f : wA;
            sA += wA;
            __half2 wA2 = __float2half2_rn(wA);
            uint4 vr = *(const uint4*)&VS[k * 8];
            const __half2* vh = (const __half2*)&vr;
#pragma unroll
            for (int d = 0; d < 4; d++)
                a[d] = __hfma2(wA2, vh[d], a[d]);
        }
#pragma unroll
        for (int d = 0; d < 4; d++) {
            float2 fa = __half22float2(a[d]);
            acc[2 * d] += fa.x;
            acc[2 * d + 1] += fa.y;
        }
    }

    // same-type column: 15 keys
    {
        __half2 a[4] = {hz, hz, hz, hz};
#pragma unroll
        for (int t = 0; t < 16; t++) {
            if (t == tq) continue;
            int k = (t << 6) + vq;
            uint4 kr = *(const uint4*)&KS[k * 8];
            float dA = dot_h2(q2, kr);
            float wA = __expf(dA);
            wA = zs[k] ? 0.0f : wA;
            sA += wA;
            __half2 wA2 = __float2half2_rn(wA);
            uint4 vr = *(const uint4*)&VS[k * 8];
            const __half2* vh = (const __half2*)&vr;
#pragma unroll
            for (int d = 0; d < 4; d++) a[d] = __hfma2(wA2, vh[d], a[d]);
        }
#pragma unroll
        for (int d = 0; d < 4; d++) {
            float2 fa = __half22float2(a[d]);
            acc[2 * d] += fa.x;
            acc[2 * d + 1] += fa.y;
        }
    }

    float inv = 1.0f / sA;
    __half* o = out + ((size_t)(b * LL + q)) * EE + h * 8;
    uint4 pk;
    pk.x = pack2h(acc[0] * inv, acc[1] * inv);
    pk.y = pack2h(acc[2] * inv, acc[3] * inv);
    pk.z = pack2h(acc[4] * inv, acc[5] * inv);
    pk.w = pack2h(acc[6] * inv, acc[7] * inv);
    *(uint4*)o = pk;
}

// ---------------- fused Wo+LN1+FFN+LN2 (fp16), 128 rows/block, 256 thr (R12 version) ----------------
#define XS_OFF 0
#define HS_OFF 18432
#define WS_OFF 36864
#define WS_STRIDE 18432
#define FBUF_OFF 36864
#define FFN_SMEM 73728

__global__ __launch_bounds__(256) void wo_ffn_fused(const __half* __restrict__ attnh,
                                                    const __half* __restrict__ woT,
                                                    const float* __restrict__ bo,
                                                    const float* __restrict__ ln1_s,
                                                    const float* __restrict__ ln1_b,
                                                    const __half* __restrict__ w1T,
                                                    const __half* __restrict__ w2T,
                                                    const float* __restrict__ b1,
                                                    const float* __restrict__ b2,
                                                    const float* __restrict__ ln2_s,
                                                    const float* __restrict__ ln2_b,
                                                    float* __restrict__ x,
                                                    __half* __restrict__ xh)
{
    extern __shared__ __align__(16) char sm[];
    __half* XS = (__half*)(sm + XS_OFF);
    __half* HS = (__half*)(sm + HS_OFF);
    float* buf = (float*)(sm + FBUF_OFF);
    unsigned smem_base = (unsigned)__cvta_generic_to_shared(sm);

    int tid = threadIdx.x;
    int w = tid >> 5, lane = tid & 31;
    int wm = w >> 1, wn = w & 1;
    int rm = wm * 32, cn = wn * 32;
    int row0 = blockIdx.x * 128;
    int gr = lane >> 2, gc = (lane & 3) * 2;

    int a_row = (lane & 7) + ((lane >> 3) & 1) * 8;
    int a_col = (lane >> 4) * 8;
    int b_row = (lane & 7) + ((lane >> 4) & 1) * 8;
    int b_col = ((lane >> 3) & 1) * 8;
    unsigned aoff = (unsigned)(((rm + a_row) * SPH + a_col) * 2);
    unsigned boff = (unsigned)(((cn + b_row) * SPH + b_col) * 2);

    unsigned xs_b = smem_base + XS_OFF;
    unsigned hs_b = smem_base + HS_OFF;

    // group A: attnh tile -> XS + Wo weights -> HS
    {
        int r = tid >> 1, sb = (tid & 1) * 4;
        const __half* src = attnh + (size_t)(row0 + r) * 64;
#pragma unroll
        for (int j = 0; j < 4; j++)
            CP_ASYNC16(xs_b + r * 144 + (sb + j) * 16, src + (sb + j) * 8);
        int n = tid >> 2, seg0 = (tid & 3) * 2;
        CP_ASYNC16(hs_b + n * 144 + seg0 * 16, woT + n * 64 + seg0 * 8);
        CP_ASYNC16(hs_b + n * 144 + (seg0 + 1) * 16, woT + n * 64 + (seg0 + 1) * 8);
    }
    CP_COMMIT();

    // group B: ffn chunk 0 -> WS stage 0
    int wr = tid >> 2, ws0 = (tid & 3) * 2;
    unsigned wdst = (unsigned)(wr * 144 + ws0 * 16);
    int wsrc = wr * 64 + ws0 * 8;
    {
        unsigned st = smem_base + WS_OFF;
        CP_ASYNC16(st + wdst, w1T + wsrc);
        CP_ASYNC16(st + wdst + 16, w1T + wsrc + 8);
        CP_ASYNC16(st + 9216 + wdst, w2T + wsrc);
        CP_ASYNC16(st + 9216 + wdst + 16, w2T + wsrc + 8);
    }
    CP_COMMIT();
    CP_WAIT1();
    __syncthreads();

    // ---- Wo GEMM ----
    float oacc[2][4][4];
#pragma unroll
    for (int i = 0; i < 2; i++)
#pragma unroll
        for (int j = 0; j < 4; j++)
#pragma unroll
            for (int r = 0; r < 4; r++) oacc[i][j][r] = 0.0f;

#pragma unroll
    for (int kt = 0; kt < 4; kt++) {
        unsigned kko = (unsigned)(kt * 32);
        unsigned a[2][4], bf[2][4];
        ldsm_x4(a[0], xs_b + aoff + kko);
        ldsm_x4(a[1], xs_b + aoff + 16 * 144 + kko);
        ldsm_x4(bf[0], hs_b + boff + kko);
        ldsm_x4(bf[1], hs_b + boff + 16 * 144 + kko);
#pragma unroll
        for (int mi = 0; mi < 2; mi++)
#pragma unroll
            for (int p = 0; p < 2; p++) {
                mma_f16(oacc[mi][p * 2],     a[mi], &bf[p][0]);
                mma_f16(oacc[mi][p * 2 + 1], a[mi], &bf[p][2]);
            }
    }
    __syncthreads();

#pragma unroll
    for (int mi = 0; mi < 2; mi++)
#pragma unroll
        for (int ni = 0; ni < 4; ni++) {
            int cl = cn + ni * 8 + gc;
            float bb0 = bo[cl], bb1 = bo[cl + 1];
            int r0 = rm + mi * 16 + gr;
            *(unsigned*)&HS[r0 * SPH + cl] = pack2h(oacc[mi][ni][0] + bb0, oacc[mi][ni][1] + bb1);
            *(unsigned*)&HS[(r0 + 8) * SPH + cl] = pack2h(oacc[mi][ni][2] + bb0, oacc[mi][ni][3] + bb1);
        }
    __syncthreads();

    // ---- LN1: x1 = LN(o + x_res); keep fp32 in regs, write fp16 to XS ----
    float xr0[16], xr1[16];
#pragma unroll
    for (int rr = 0; rr < 16; rr++) {
        int row = w * 16 + rr;
        size_t go = (size_t)(row0 + row) * 64;
        float y0 = __half2float(HS[row * SPH + lane]) + x[go + lane];
        float y1 = __half2float(HS[row * SPH + lane + 32]) + x[go + lane + 32];
        float mean = warp_sum32(y0 + y1) * (1.0f / 64.0f);
        float d0 = y0 - mean, d1 = y1 - mean;
        float var = warp_sum32(d0 * d0 + d1 * d1) * (1.0f / 64.0f);
        float inv = rsqrtf(var + 1e-5f);
        float o0 = d0 * inv * ln1_s[lane] + ln1_b[lane];
        float o1 = d1 * inv * ln1_s[lane + 32] + ln1_b[lane + 32];
        xr0[rr] = o0;
        xr1[rr] = o1;
        XS[row * SPH + lane] = __float2half_rn(o0);
        XS[row * SPH + lane + 32] = __float2half_rn(o1);
    }
    __syncthreads();

    // ---- FFN main loop (3-sync version) ----
    float acc2[2][4][4];
#pragma unroll
    for (int i = 0; i < 2; i++)
#pragma unroll
        for (int j = 0; j < 4; j++)
#pragma unroll
            for (int r = 0; r < 4; r++) acc2[i][j][r] = 0.0f;

    for (int c = 0; c < 32; c++) {
        int s = c & 1;
        if (c + 1 < 32) {
            unsigned st = smem_base + WS_OFF + (s ^ 1) * WS_STRIDE;
            int src = (c + 1) * 4096 + wsrc;
            CP_ASYNC16(st + wdst, w1T + src);
            CP_ASYNC16(st + wdst + 16, w1T + src + 8);
            CP_ASYNC16(st + 9216 + wdst, w2T + src);
            CP_ASYNC16(st + 9216 + wdst + 16, w2T + src + 8);
        }
        CP_COMMIT();
        CP_WAIT1();
        __syncthreads();

        unsigned w1_b = smem_base + WS_OFF + s * WS_STRIDE;
        unsigned w2_b = w1_b + 9216;

        float hacc[2][4][4];
#pragma unroll
        for (int i = 0; i < 2; i++)
#pragma unroll
            for (int j = 0; j < 4; j++)
#pragma unroll
                for (int r = 0; r < 4; r++) hacc[i][j][r] = 0.0f;

#pragma unroll
        for (int kt = 0; kt < 4; kt++) {
            unsigned kko = (unsigned)(kt * 32);
            unsigned a[2][4], bf[2][4];
            ldsm_x4(a[0], xs_b + aoff + kko);
            ldsm_x4(a[1], xs_b + aoff + 16 * 144 + kko);
            ldsm_x4(bf[0], w1_b + boff + kko);
            ldsm_x4(bf[1], w1_b + boff + 16 * 144 + kko);
#pragma unroll
            for (int mi = 0; mi < 2; mi++)
#pragma unroll
                for (int p = 0; p < 2; p++) {
                    mma_f16(hacc[mi][p * 2],     a[mi], &bf[p][0]);
                    mma_f16(hacc[mi][p * 2 + 1], a[mi], &bf[p][2]);
                }
        }

#pragma unroll
        for (int mi = 0; mi < 2; mi++)
#pragma unroll
            for (int ni = 0; ni < 4; ni++) {
                int cl = cn + ni * 8 + gc;
                int cg = c * 64 + cl;
                float bb0 = b1[cg], bb1 = b1[cg + 1];
                float v0 = fmaxf(hacc[mi][ni][0] + bb0, 0.0f);
                float v1 = fmaxf(hacc[mi][ni][1] + bb1, 0.0f);
                float v2 = fmaxf(hacc[mi][ni][2] + bb0, 0.0f);
                float v3 = fmaxf(hacc[mi][ni][3] + bb1, 0.0f);
                *(unsigned*)&HS[(rm + mi * 16 + gr) * SPH + cl] = pack2h(v0, v1);
                *(unsigned*)&HS[(rm + mi * 16 + gr + 8) * SPH + cl] = pack2h(v2, v3);
            }
        __syncthreads();

#pragma unroll
        for (int kt = 0; kt < 4; kt++) {
            unsigned kko = (unsigned)(kt * 32);
            unsigned a[2][4], bf[2][4];
            ldsm_x4(a[0], hs_b + aoff + kko);
            ldsm_x4(a[1], hs_b + aoff + 16 * 144 + kko);
            ldsm_x4(bf[0], w2_b + boff + kko);
            ldsm_x4(bf[1], w2_b + boff + 16 * 144 + kko);
#pragma unroll
            for (int mi = 0; mi < 2; mi++)
#pragma unroll
                for (int p = 0; p < 2; p++) {
                    mma_f16(acc2[mi][p * 2],     a[mi], &bf[p][0]);
                    mma_f16(acc2[mi][p * 2 + 1], a[mi], &bf[p][2]);
                }
        }
        __syncthreads();
    }

    // epilogue: + b2 -> buf, + residual(regs), LN2
#pragma unroll
    for (int mi = 0; mi < 2; mi++)
#pragma unroll
        for (int ni = 0; ni < 4; ni++) {
            int cc = cn + ni * 8 + gc;
            float b0 = b2[cc], b1v = b2[cc + 1];
            int r0 = rm + mi * 16 + gr;
            buf[r0 * 65 + cc] = acc2[mi][ni][0] + b0;
            buf[r0 * 65 + cc + 1] = acc2[mi][ni][1] + b1v;
            buf[(r0 + 8) * 65 + cc] = acc2[mi][ni][2] + b0;
            buf[(r0 + 8) * 65 + cc + 1] = acc2[mi][ni][3] + b1v;
        }
    __syncthreads();

#pragma unroll
    for (int rr = 0; rr < 16; rr++) {
        int row = w * 16 + rr;
        size_t go = (size_t)(row0 + row) * 64;
        float y0 = buf[row * 65 + lane] + xr0[rr];
        float y1 = buf[row * 65 + lane + 32] + xr1[rr];
        float mean = warp_sum32(y0 + y1) * (1.0f / 64.0f);
        float d0 = y0 - mean, d1 = y1 - mean;
        float var = warp_sum32(d0 * d0 + d1 * d1) * (1.0f / 64.0f);
        float inv = rsqrtf(var + 1e-5f);
        float o0 = d0 * inv * ln2_s[lane] + ln2_b[lane];
        float o1 = d1 * inv * ln2_s[lane + 32] + ln2_b[lane + 32];
        x[go + lane] = o0;
        x[go + lane + 32] = o1;
        xh[go + lane] = __float2half_rn(o0);
        xh[go + lane + 32] = __float2half_rn(o1);
    }
}

// ---------------- head ----------------
__global__ void head_kernel(const float* __restrict__ x,
                            const float* __restrict__ W_head,
                            const float* __restrict__ b_head,
                            float* __restrict__ out)
{
    int b = blockIdx.x;
    int tid = threadIdx.x;  // 192
    int v = tid / 3, c = tid % 3;
    const float* row = x + ((size_t)(b * LL + (SS - 1) * VV + v)) * EE;
    float acc = b_head[c];
#pragma unroll
    for (int e = 0; e < EE; e++) acc += row[e] * W_head[e * 3 + c];
    out[b * (VV * 3) + tid] = acc;
}

// ---------------- launch ----------------
extern "C" void kernel_launch(void* const* d_in, const int* in_sizes, int n_in,
                              void* d_out, int out_size)
{
    const float* features    = (const float*)d_in[0];
    const int*   overlap_tag = (const int*)d_in[1];
    const int*   poi_id      = (const int*)d_in[2];
    const float* W_raw       = (const float*)d_in[3];
    const float* b_raw       = (const float*)d_in[4];
    const float* pos_tab     = (const float*)d_in[5];
    const float* type_tab    = (const float*)d_in[6];
    const float* poi_tab     = (const float*)d_in[7];
    const float* overlap_tab = (const float*)d_in[8];
    const float* W_comb      = (const float*)d_in[9];
    const float* b_comb      = (const float*)d_in[10];
    const float* Wqkv        = (const float*)d_in[11];
    const float* bqkv        = (const float*)d_in[12];
    const float* Wo          = (const float*)d_in[13];
    const float* bo          = (const float*)d_in[14];
    const float* ln1_s       = (const float*)d_in[15];
    const float* ln1_b       = (const float*)d_in[16];
    const float* W1          = (const float*)d_in[17];
    const float* b1          = (const float*)d_in[18];
    const float* W2          = (const float*)d_in[19];
    const float* b2          = (const float*)d_in[20];
    const float* ln2_s       = (const float*)d_in[21];
    const float* ln2_b       = (const float*)d_in[22];
    const float* W_head      = (const float*)d_in[23];
    const float* b_head      = (const float*)d_in[24];
    float* out = (float*)d_out;

    float *x;
    __half *xh, *attnh, *qkvT, *woT, *w1T, *w2T;
    unsigned char* zero;
    cudaGetSymbolAddress((void**)&x,     g_x);
    cudaGetSymbolAddress((void**)&xh,    g_xh);
    cudaGetSymbolAddress((void**)&attnh, g_attnh);
    cudaGetSymbolAddress((void**)&zero,  g_zero);
    cudaGetSymbolAddress((void**)&qkvT,  g_qkvT);
    cudaGetSymbolAddress((void**)&woT,   g_woT);
    cudaGetSymbolAddress((void**)&w1T,   g_w1T);
    cudaGetSymbolAddress((void**)&w2T,   g_w2T);

    cudaFuncSetAttribute(attn_kernel, cudaFuncAttributeMaxDynamicSharedMemorySize, ATTN_SMEM);
    cudaFuncSetAttribute(wo_ffn_fused, cudaFuncAttributeMaxDynamicSharedMemorySize, FFN_SMEM);

    prep_weights<<<dim3(256, 4), 256>>>(Wqkv, Wo, W1, W2);

    embed_kernel<<<ML, 64>>>(features, overlap_tag, poi_id, W_raw, b_raw,
                             pos_tab, type_tab, poi_tab, overlap_tab,
                             W_comb, b_comb, x, xh, zero);

    for (int l = 0; l < NL; l++) {
        attn_kernel<<<BB * HH, 1024, ATTN_SMEM>>>(
            xh, qkvT + l * 12288, bqkv + l * 192, zero, attnh);
        wo_ffn_fused<<<ML / 128, 256, FFN_SMEM>>>(
            attnh, woT + l * 4096, bo + l * EE,
            ln1_s + l * EE, ln1_b + l * EE,
            w1T + l * DFF * 64, w2T + l * DFF * 64,
            b1 + l * DFF, b2 + l * EE,
            ln2_s + l * EE, ln2_b + l * EE,
            x, xh);
    }

    head_kernel<<<BB, VV * 3>>>(x, W_head, b_head, out);
}

// round 17
// speedup vs baseline: 1.1930x; 1.0089x over previous
#include <cuda_runtime.h>
#include <cuda_fp16.h>
#include <math.h>

#define BB 16
#define SS 16
#define VV 64
#define EE 64
#define HH 8
#define NL 4
#define DFF 2048
#define LL 1024
#define ML (BB*LL)
#define SPH 72   // smem row stride in halves (64 data + 8 pad) = 144 bytes

// ---------------- scratch ----------------
__device__ float g_x[ML * EE];            // fp32 residual stream
__device__ __half g_xh[ML * EE];          // fp16 copy of x
__device__ __half g_attnh[ML * EE];       // attention output (fp16)
__device__ unsigned char g_zero[ML];

// pre-converted transposed fp16 weights ([n][k])
__device__ __align__(256) __half g_qkvT[NL * 192 * 64];
__device__ __align__(256) __half g_woT[NL * 64 * 64];
__device__ __align__(256) __half g_w1T[NL * DFF * 64];
__device__ __align__(256) __half g_w2T[NL * DFF * 64];

// ---------------- helpers ----------------
__device__ __forceinline__ unsigned pack2h(float a, float b) {
    __half2 h = __floats2half2_rn(a, b);
    return *(unsigned*)&h;
}
__device__ __forceinline__ void mma_f16(float* c, const unsigned* a, const unsigned* b) {
    asm volatile(
        "mma.sync.aligned.m16n8k16.row.col.f32.f16.f16.f32 "
        "{%0,%1,%2,%3}, {%4,%5,%6,%7}, {%8,%9}, {%0,%1,%2,%3};\n"
        : "+f"(c[0]), "+f"(c[1]), "+f"(c[2]), "+f"(c[3])
        : "r"(a[0]), "r"(a[1]), "r"(a[2]), "r"(a[3]), "r"(b[0]), "r"(b[1]));
}
__device__ __forceinline__ void ldsm_x4(unsigned* r, unsigned addr) {
    asm volatile("ldmatrix.sync.aligned.m8n8.x4.shared.b16 {%0,%1,%2,%3}, [%4];\n"
        : "=r"(r[0]), "=r"(r[1]), "=r"(r[2]), "=r"(r[3]) : "r"(addr));
}
__device__ __forceinline__ float warp_sum32(float v) {
#pragma unroll
    for (int o = 16; o > 0; o >>= 1) v += __shfl_xor_sync(0xffffffffu, v, o);
    return v;
}
#define CP_ASYNC16(dst, src) \
    asm volatile("cp.async.ca.shared.global [%0], [%1], 16;\n" :: "r"(dst), "l"(src))
#define CP_COMMIT() asm volatile("cp.async.commit_group;\n")
#define CP_WAIT1()  asm volatile("cp.async.wait_group 1;\n")
#define CP_WAIT0()  asm volatile("cp.async.wait_group 0;\n")

// ---------------- weight prep: coalesced tiled transpose ----------------
__global__ __launch_bounds__(256) void prep_weights(const float* __restrict__ Wqkv,
                                                    const float* __restrict__ Wo,
                                                    const float* __restrict__ W1,
                                                    const float* __restrict__ W2)
{
    __shared__ float s[64 * 65];
    int tid = threadIdx.x;
    int bx = blockIdx.x, which = blockIdx.y;

    if (which == 0) {
        if (bx >= NL * 6) return;
        int layer = bx / 6, n0 = (bx % 6) * 32;
        for (int i = tid; i < 2048; i += 256) {
            int k = i >> 5, n = i & 31;
            s[k * 33 + n] = Wqkv[(size_t)layer * 12288 + k * 192 + n0 + n];
        }
        __syncthreads();
        for (int i = tid; i < 2048; i += 256) {
            int n = i >> 6, k = i & 63;
            g_qkvT[(size_t)layer * 12288 + (n0 + n) * 64 + k] = __float2half_rn(s[k * 33 + n]);
        }
    } else if (which == 1) {
        if (bx >= NL * 2) return;
        int layer = bx / 2, n0 = (bx % 2) * 32;
        for (int i = tid; i < 2048; i += 256) {
            int k = i >> 5, n = i & 31;
            s[k * 33 + n] = Wo[(size_t)layer * 4096 + k * 64 + n0 + n];
        }
        __syncthreads();
        for (int i = tid; i < 2048; i += 256) {
            int n = i >> 6, k = i & 63;
            g_woT[(size_t)layer * 4096 + (n0 + n) * 64 + k] = __float2half_rn(s[k * 33 + n]);
        }
    } else if (which == 2) {
        if (bx >= NL * 64) return;
        int layer = bx / 64, n0 = (bx % 64) * 32;
        for (int i = tid; i < 2048; i += 256) {
            int k = i >> 5, n = i & 31;
            s[k * 33 + n] = W1[(size_t)layer * DFF * 64 + k * DFF + n0 + n];
        }
        __syncthreads();
        for (int i = tid; i < 2048; i += 256) {
            int n = i >> 6, k = i & 63;
            g_w1T[(size_t)layer * DFF * 64 + (n0 + n) * 64 + k] = __float2half_rn(s[k * 33 + n]);
        }
    } else {
        if (bx >= NL * 32) return;
        int layer = bx / 32, c = bx % 32;
        for (int i = tid; i < 4096; i += 256) {
            int kl = i >> 6, n = i & 63;
            s[kl * 65 + n] = W2[(size_t)layer * DFF * 64 + (c * 64 + kl) * 64 + n];
        }
        __syncthreads();
        for (int i = tid; i < 4096; i += 256) {
            int n = i >> 6, kl = i & 63;
            g_w2T[(size_t)layer * DFF * 64 + c * 4096 + n * 64 + kl] = __float2half_rn(s[kl * 65 + n]);
        }
    }
}

// ---------------- embed ----------------
__global__ void embed_kernel(const float* __restrict__ features,
                             const int* __restrict__ overlap_tag,
                             const int* __restrict__ poi_id,
                             const float* __restrict__ W_raw,
                             const float* __restrict__ b_raw,
                             const float* __restrict__ pos_tab,
                             const float* __restrict__ type_tab,
                             const float* __restrict__ poi_tab,
                             const float* __restrict__ overlap_tab,
                             const float* __restrict__ W_comb,
                             const float* __restrict__ b_comb,
                             float* __restrict__ x,
                             __half* __restrict__ xh,
                             unsigned char* __restrict__ zero_mask)
{
    int bl = blockIdx.x;
    int l  = bl & (LL - 1);
    int s  = l >> 6;
    int v  = l & 63;
    int tid = threadIdx.x;  // 64

    __shared__ float concat[80];
    const float* f = features + (size_t)bl * 3;
    float f0 = f[0], f1 = f[1], f2 = f[2];

    concat[tid] = f0 * W_raw[tid] + f1 * W_raw[64 + tid] + f2 * W_raw[128 + tid] + b_raw[tid];
    if (tid < 8) {
        int ov = overlap_tag[bl];
        concat[64 + tid] = (ov == 0) ? 0.0f : overlap_tab[ov * 8 + tid];
        int poi = poi_id[bl];
        concat[72 + tid] = (poi == 0) ? 0.0f : poi_tab[poi * 8 + tid];
    }
    if (tid == 0) zero_mask[bl] = (f0 + f1 + f2 == 0.0f) ? 1 : 0;
    __syncthreads();

    float acc = b_comb[tid];
#pragma unroll
    for (int j = 0; j < 80; j++) acc += concat[j] * W_comb[j * EE + tid];
    acc += pos_tab[s * EE + tid] + type_tab[v * EE + tid];
    x[(size_t)bl * EE + tid] = acc;
    xh[(size_t)bl * EE + tid] = __float2half_rn(acc);
}

// ---------------- fused QKV + attention: one block per (b,h), 1024 threads ----------------
#define XH_OFF 0
#define WQ_OFF 147456
#define QS_OFF 152064
#define KS_OFF 168448
#define VS_OFF 184832
#define ZS_OFF 201216
#define ATTN_SMEM 202240

__device__ __forceinline__ float dot_h2(const __half2* q2, const uint4& kr) {
    const __half2* kh = (const __half2*)&kr;
    __half2 d = __hmul2(q2[0], kh[0]);
    d = __hfma2(q2[1], kh[1], d);
    d = __hfma2(q2[2], kh[2], d);
    d = __hfma2(q2[3], kh[3], d);
    return __low2float(d) + __high2float(d);
}

__global__ __launch_bounds__(1024) void attn_kernel(const __half* __restrict__ xh,
                                                    const __half* __restrict__ qkvT,
                                                    const float* __restrict__ bqkv,
                                                    const unsigned char* __restrict__ zero_mask,
                                                    __half* __restrict__ out)
{
    extern __shared__ char smc[];
    __half* XH = (__half*)(smc + XH_OFF);
    __half* QS = (__half*)(smc + QS_OFF);
    __half* KS = (__half*)(smc + KS_OFF);
    __half* VS = (__half*)(smc + VS_OFF);
    unsigned char* zs = (unsigned char*)(smc + ZS_OFF);
    unsigned sb = (unsigned)__cvta_generic_to_shared(smc);

    int bh = blockIdx.x;                  // 128 blocks
    int b = bh >> 3, h = bh & 7;
    int tid = threadIdx.x;                // 1024
    int w = tid >> 5, lane = tid & 31;

    const __half* xsrc = xh + (size_t)b * LL * 64;
#pragma unroll
    for (int it = 0; it < 8; it++) {
        int i = tid + it * 1024;
        int r = i >> 3, seg = i & 7;
        CP_ASYNC16(sb + XH_OFF + r * 144 + seg * 16, xsrc + r * 64 + seg * 8);
    }
    if (tid < 192) {
        int n = tid >> 3, seg = tid & 7;
        int ni = n >> 3;
        int gn = ni * 64 + h * 8 + (n & 7);
        CP_ASYNC16(sb + WQ_OFF + n * 144 + seg * 16, qkvT + gn * 64 + seg * 8);
    }
    zs[tid] = zero_mask[b * LL + tid];
    CP_COMMIT();
    CP_WAIT0();
    __syncthreads();

    // ---- QKV MMA phase: warp w handles rows [w*32, w*32+32) ----
    {
        int rm = w * 32;
        int gr = lane >> 2, gc = (lane & 3) * 2;
        float acc[2][3][4];
#pragma unroll
        for (int mi = 0; mi < 2; mi++)
#pragma unroll
            for (int ni = 0; ni < 3; ni++)
#pragma unroll
                for (int r = 0; r < 4; r++) acc[mi][ni][r] = 0.0f;

        const __half* WQ = (const __half*)(smc + WQ_OFF);
#pragma unroll
        for (int kt = 0; kt < 4; kt++) {
            int kk = kt * 16;
            unsigned a[2][4], bf[3][2];
#pragma unroll
            for (int mi = 0; mi < 2; mi++) {
                int r = rm + mi * 16;
                a[mi][0] = *(unsigned*)&XH[(r + gr) * SPH + kk + gc];
                a[mi][1] = *(unsigned*)&XH[(r + gr + 8) * SPH + kk + gc];
                a[mi][2] = *(unsigned*)&XH[(r + gr) * SPH + kk + gc + 8];
                a[mi][3] = *(unsigned*)&XH[(r + gr + 8) * SPH + kk + gc + 8];
            }
#pragma unroll
            for (int ni = 0; ni < 3; ni++) {
                int n = ni * 8 + gr;
                bf[ni][0] = *(unsigned*)&WQ[n * SPH + kk + gc];
                bf[ni][1] = *(unsigned*)&WQ[n * SPH + kk + gc + 8];
            }
#pragma unroll
            for (int mi = 0; mi < 2; mi++)
#pragma unroll
                for (int ni = 0; ni < 3; ni++)
                    mma_f16(acc[mi][ni], a[mi], bf[ni]);
        }

        const float qsc = 0.35355339059327373f;
#pragma unroll
        for (int mi = 0; mi < 2; mi++) {
            int r0 = rm + mi * 16 + gr;
#pragma unroll
            for (int ni = 0; ni < 3; ni++) {
                __half* op = (ni == 0) ? QS : ((ni == 1) ? KS : VS);
                float sc = (ni == 0) ? qsc : 1.0f;
                float b0 = bqkv[ni * 64 + h * 8 + gc];
                float b1 = bqkv[ni * 64 + h * 8 + gc + 1];
                *(unsigned*)&op[r0 * 8 + gc] =
                    pack2h((acc[mi][ni][0] + b0) * sc, (acc[mi][ni][1] + b1) * sc);
                *(unsigned*)&op[(r0 + 8) * 8 + gc] =
                    pack2h((acc[mi][ni][2] + b0) * sc, (acc[mi][ni][3] + b1) * sc);
            }
        }
    }
    __syncthreads();

    // ---- attention: 1 query/thread ----
    int q = tid;
    int tq = q >> 6;
    int vq = q & 63;

    uint4 qr = *(const uint4*)&QS[q * 8];
    const __half2* q2 = (const __half2*)&qr;

    float sA = 0.0f;
    float acc[8] = {};
    const __half2 hz = __floats2half2_rn(0.0f, 0.0f);

    int kb = tq << 6;
#pragma unroll
    for (int ch = 0; ch < 4; ch++) {
        __half2 a[4] = {hz, hz, hz, hz};
#pragma unroll
        for (int j = 0; j < 16; j++) {
            int k = kb + ch * 16 + j;
            uint4 kr = *(const uint4*)&KS[k * 8];
            float dA = dot_h2(q2, kr);
            float wA = __expf(dA);
            wA = zs[k] ? 0.0f : wA;
            sA += wA;
            __half2 wA2 = __float2half2_rn(wA);
            uint4 vr = *(const uint4*)&VS[k * 8];
            const __half2* vh = (const __half2*)&vr;
#pragma unroll
            for (int d = 0; d < 4; d++)
                a[d] = __hfma2(wA2, vh[d], a[d]);
        }
#pragma unroll
        for (int d = 0; d < 4; d++) {
            float2 fa = __half22float2(a[d]);
            acc[2 * d] += fa.x;
            acc[2 * d + 1] += fa.y;
        }
    }

    {
        __half2 a[4] = {hz, hz, hz, hz};
#pragma unroll
        for (int t = 0; t < 16; t++) {
            if (t == tq) continue;
            int k = (t << 6) + vq;
            uint4 kr = *(const uint4*)&KS[k * 8];
            float dA = dot_h2(q2, kr);
            float wA = __expf(dA);
            wA = zs[k] ? 0.0f : wA;
            sA += wA;
            __half2 wA2 = __float2half2_rn(wA);
            uint4 vr = *(const uint4*)&VS[k * 8];
            const __half2* vh = (const __half2*)&vr;
#pragma unroll
            for (int d = 0; d < 4; d++) a[d] = __hfma2(wA2, vh[d], a[d]);
        }
#pragma unroll
        for (int d = 0; d < 4; d++) {
            float2 fa = __half22float2(a[d]);
            acc[2 * d] += fa.x;
            acc[2 * d + 1] += fa.y;
        }
    }

    float inv = 1.0f / sA;
    __half* o = out + ((size_t)(b * LL + q)) * EE + h * 8;
    uint4 pk;
    pk.x = pack2h(acc[0] * inv, acc[1] * inv);
    pk.y = pack2h(acc[2] * inv, acc[3] * inv);
    pk.z = pack2h(acc[4] * inv, acc[5] * inv);
    pk.w = pack2h(acc[6] * inv, acc[7] * inv);
    *(uint4*)o = pk;
}

// ---------------- fused Wo+LN1+FFN+LN2, super-chunked (2 DFF-chunks/iter) ----------------
// smem (bytes):
//   XS:   0      .. 18432   attnh tile, then post-LN1 x
//   HS0:  18432  .. 36864   Wo weights / o-proj / ffn h(c0)
//   HS1:  36864  .. 55296   ffn h(c1)
//   WS:   55296  .. 129024  (2 stages * 36864; stage = W1(c0),W2(c0),W1(c1),W2(c1))
//   buf:  aliases WS
#define XS_OFF 0
#define HS_OFF 18432
#define HS1_OFF 36864
#define WS_OFF 55296
#define WS_STRIDE 36864
#define FBUF_OFF 55296
#define FFN_SMEM 129024

__global__ __launch_bounds__(256) void wo_ffn_fused(const __half* __restrict__ attnh,
                                                    const __half* __restrict__ woT,
                                                    const float* __restrict__ bo,
                                                    const float* __restrict__ ln1_s,
                                                    const float* __restrict__ ln1_b,
                                                    const __half* __restrict__ w1T,
                                                    const __half* __restrict__ w2T,
                                                    const float* __restrict__ b1,
                                                    const float* __restrict__ b2,
                                                    const float* __restrict__ ln2_s,
                                                    const float* __restrict__ ln2_b,
                                                    float* __restrict__ x,
                                                    __half* __restrict__ xh)
{
    extern __shared__ __align__(16) char sm[];
    __half* XS = (__half*)(sm + XS_OFF);
    __half* HS0 = (__half*)(sm + HS_OFF);
    __half* HS1 = (__half*)(sm + HS1_OFF);
    float* buf = (float*)(sm + FBUF_OFF);
    unsigned smem_base = (unsigned)__cvta_generic_to_shared(sm);

    int tid = threadIdx.x;
    int w = tid >> 5, lane = tid & 31;
    int wm = w >> 1, wn = w & 1;
    int rm = wm * 32, cn = wn * 32;
    int row0 = blockIdx.x * 128;
    int gr = lane >> 2, gc = (lane & 3) * 2;

    int a_row = (lane & 7) + ((lane >> 3) & 1) * 8;
    int a_col = (lane >> 4) * 8;
    int b_row = (lane & 7) + ((lane >> 4) & 1) * 8;
    int b_col = ((lane >> 3) & 1) * 8;
    unsigned aoff = (unsigned)(((rm + a_row) * SPH + a_col) * 2);
    unsigned boff = (unsigned)(((cn + b_row) * SPH + b_col) * 2);

    unsigned xs_b = smem_base + XS_OFF;
    unsigned hs0_b = smem_base + HS_OFF;
    unsigned hs1_b = smem_base + HS1_OFF;

    // group A: attnh tile -> XS + Wo weights -> HS0
    {
        int r = tid >> 1, sb = (tid & 1) * 4;
        const __half* src = attnh + (size_t)(row0 + r) * 64;
#pragma unroll
        for (int j = 0; j < 4; j++)
            CP_ASYNC16(xs_b + r * 144 + (sb + j) * 16, src + (sb + j) * 8);
        int n = tid >> 2, seg0 = (tid & 3) * 2;
        CP_ASYNC16(hs0_b + n * 144 + seg0 * 16, woT + n * 64 + seg0 * 8);
        CP_ASYNC16(hs0_b + n * 144 + (seg0 + 1) * 16, woT + n * 64 + (seg0 + 1) * 8);
    }
    CP_COMMIT();

    // group B: super-chunk 0 weights (W1(0),W2(0),W1(1),W2(1)) -> WS stage 0
    int wr = tid >> 2, ws0 = (tid & 3) * 2;
    unsigned wdst = (unsigned)(wr * 144 + ws0 * 16);
    int wsrc = wr * 64 + ws0 * 8;
    {
        unsigned st = smem_base + WS_OFF;
        CP_ASYNC16(st + wdst, w1T + wsrc);
        CP_ASYNC16(st + wdst + 16, w1T + wsrc + 8);
        CP_ASYNC16(st + 9216 + wdst, w2T + wsrc);
        CP_ASYNC16(st + 9216 + wdst + 16, w2T + wsrc + 8);
        CP_ASYNC16(st + 18432 + wdst, w1T + 4096 + wsrc);
        CP_ASYNC16(st + 18432 + wdst + 16, w1T + 4096 + wsrc + 8);
        CP_ASYNC16(st + 27648 + wdst, w2T + 4096 + wsrc);
        CP_ASYNC16(st + 27648 + wdst + 16, w2T + 4096 + wsrc + 8);
    }
    CP_COMMIT();
    CP_WAIT1();           // group A done
    __syncthreads();

    // ---- Wo GEMM ----
    float oacc[2][4][4];
#pragma unroll
    for (int i = 0; i < 2; i++)
#pragma unroll
        for (int j = 0; j < 4; j++)
#pragma unroll
            for (int r = 0; r < 4; r++) oacc[i][j][r] = 0.0f;

#pragma unroll
    for (int kt = 0; kt < 4; kt++) {
        unsigned kko = (unsigned)(kt * 32);
        unsigned a[2][4], bf[2][4];
        ldsm_x4(a[0], xs_b + aoff + kko);
        ldsm_x4(a[1], xs_b + aoff + 16 * 144 + kko);
        ldsm_x4(bf[0], hs0_b + boff + kko);
        ldsm_x4(bf[1], hs0_b + boff + 16 * 144 + kko);
#pragma unroll
        for (int mi = 0; mi < 2; mi++)
#pragma unroll
            for (int p = 0; p < 2; p++) {
                mma_f16(oacc[mi][p * 2],     a[mi], &bf[p][0]);
                mma_f16(oacc[mi][p * 2 + 1], a[mi], &bf[p][2]);
            }
    }
    __syncthreads();

#pragma unroll
    for (int mi = 0; mi < 2; mi++)
#pragma unroll
        for (int ni = 0; ni < 4; ni++) {
            int cl = cn + ni * 8 + gc;
            float bb0 = bo[cl], bb1 = bo[cl + 1];
            int r0 = rm + mi * 16 + gr;
            *(unsigned*)&HS0[r0 * SPH + cl] = pack2h(oacc[mi][ni][0] + bb0, oacc[mi][ni][1] + bb1);
            *(unsigned*)&HS0[(r0 + 8) * SPH + cl] = pack2h(oacc[mi][ni][2] + bb0, oacc[mi][ni][3] + bb1);
        }
    __syncthreads();

    // ---- LN1 ----
    float xr0[16], xr1[16];
#pragma unroll
    for (int rr = 0; rr < 16; rr++) {
        int row = w * 16 + rr;
        size_t go = (size_t)(row0 + row) * 64;
        float y0 = __half2float(HS0[row * SPH + lane]) + x[go + lane];
        float y1 = __half2float(HS0[row * SPH + lane + 32]) + x[go + lane + 32];
        float mean = warp_sum32(y0 + y1) * (1.0f / 64.0f);
        float d0 = y0 - mean, d1 = y1 - mean;
        float var = warp_sum32(d0 * d0 + d1 * d1) * (1.0f / 64.0f);
        float inv = rsqrtf(var + 1e-5f);
        float o0 = d0 * inv * ln1_s[lane] + ln1_b[lane];
        float o1 = d1 * inv * ln1_s[lane + 32] + ln1_b[lane + 32];
        xr0[rr] = o0;
        xr1[rr] = o1;
        XS[row * SPH + lane] = __float2half_rn(o0);
        XS[row * SPH + lane + 32] = __float2half_rn(o1);
    }
    __syncthreads();

    // ---- FFN: 16 super-chunks of 2 chunks ----
    float acc2[2][4][4];
#pragma unroll
    for (int i = 0; i < 2; i++)
#pragma unroll
        for (int j = 0; j < 4; j++)
#pragma unroll
            for (int r = 0; r < 4; r++) acc2[i][j][r] = 0.0f;

    for (int sc = 0; sc < 16; sc++) {
        int s = sc & 1;
        CP_WAIT0();
        __syncthreads();       // stage s weights visible; all warps past GEMM2(sc-1)

        if (sc + 1 < 16) {     // prefetch next super-chunk into other stage
            unsigned st = smem_base + WS_OFF + (s ^ 1) * WS_STRIDE;
            int base0 = (2 * sc + 2) * 4096 + wsrc;
            CP_ASYNC16(st + wdst, w1T + base0);
            CP_ASYNC16(st + wdst + 16, w1T + base0 + 8);
            CP_ASYNC16(st + 9216 + wdst, w2T + base0);
            CP_ASYNC16(st + 9216 + wdst + 16, w2T + base0 + 8);
            CP_ASYNC16(st + 18432 + wdst, w1T + base0 + 4096);
            CP_ASYNC16(st + 18432 + wdst + 16, w1T + base0 + 4096 + 8);
            CP_ASYNC16(st + 27648 + wdst, w2T + base0 + 4096);
            CP_ASYNC16(st + 27648 + wdst + 16, w2T + base0 + 4096 + 8);
            CP_COMMIT();
        }

        unsigned stage = smem_base + WS_OFF + s * WS_STRIDE;

        // GEMM1 for both chunks (hacc reused sequentially)
#pragma unroll
        for (int half = 0; half < 2; half++) {
            int c = 2 * sc + half;
            unsigned w1_b = stage + half * 18432;
            unsigned hdst = half ? hs1_b : hs0_b;
            __half* HSc = half ? HS1 : HS0;

            float hacc[2][4][4];
#pragma unroll
            for (int i = 0; i < 2; i++)
#pragma unroll
                for (int j = 0; j < 4; j++)
#pragma unroll
                    for (int r = 0; r < 4; r++) hacc[i][j][r] = 0.0f;

#pragma unroll
            for (int kt = 0; kt < 4; kt++) {
                unsigned kko = (unsigned)(kt * 32);
                unsigned a[2][4], bf[2][4];
                ldsm_x4(a[0], xs_b + aoff + kko);
                ldsm_x4(a[1], xs_b + aoff + 16 * 144 + kko);
                ldsm_x4(bf[0], w1_b + boff + kko);
                ldsm_x4(bf[1], w1_b + boff + 16 * 144 + kko);
#pragma unroll
                for (int mi = 0; mi < 2; mi++)
#pragma unroll
                    for (int p = 0; p < 2; p++) {
                        mma_f16(hacc[mi][p * 2],     a[mi], &bf[p][0]);
                        mma_f16(hacc[mi][p * 2 + 1], a[mi], &bf[p][2]);
                    }
            }

#pragma unroll
            for (int mi = 0; mi < 2; mi++)
#pragma unroll
                for (int ni = 0; ni < 4; ni++) {
                    int cl = cn + ni * 8 + gc;
                    int cg = c * 64 + cl;
                    float bb0 = b1[cg], bb1 = b1[cg + 1];
                    float v0 = fmaxf(hacc[mi][ni][0] + bb0, 0.0f);
                    float v1 = fmaxf(hacc[mi][ni][1] + bb1, 0.0f);
                    float v2 = fmaxf(hacc[mi][ni][2] + bb0, 0.0f);
                    float v3 = fmaxf(hacc[mi][ni][3] + bb1, 0.0f);
                    *(unsigned*)&HSc[(rm + mi * 16 + gr) * SPH + cl] = pack2h(v0, v1);
                    *(unsigned*)&HSc[(rm + mi * 16 + gr + 8) * SPH + cl] = pack2h(v2, v3);
                }
        }
        __syncthreads();       // both H tiles visible

        // GEMM2 for both chunks, accumulating into acc2
#pragma unroll
        for (int half = 0; half < 2; half++) {
            unsigned w2_b = stage + half * 18432 + 9216;
            unsigned hsrc = half ? hs1_b : hs0_b;
#pragma unroll
            for (int kt = 0; kt < 4; kt++) {
                unsigned kko = (unsigned)(kt * 32);
                unsigned a[2][4], bf[2][4];
                ldsm_x4(a[0], hsrc + aoff + kko);
                ldsm_x4(a[1], hsrc + aoff + 16 * 144 + kko);
                ldsm_x4(bf[0], w2_b + boff + kko);
                ldsm_x4(bf[1], w2_b + boff + 16 * 144 + kko);
#pragma unroll
                for (int mi = 0; mi < 2; mi++)
#pragma unroll
                    for (int p = 0; p < 2; p++) {
                        mma_f16(acc2[mi][p * 2],     a[mi], &bf[p][0]);
                        mma_f16(acc2[mi][p * 2 + 1], a[mi], &bf[p][2]);
                    }
            }
        }
        // no trailing sync: next iteration's weight sync covers all hazards
    }
    __syncthreads();           // all GEMM2 reads done before buf (aliases WS) is written

    // epilogue: + b2 -> buf, + residual(regs), LN2
#pragma unroll
    for (int mi = 0; mi < 2; mi++)
#pragma unroll
        for (int ni = 0; ni < 4; ni++) {
            int cc = cn + ni * 8 + gc;
            float b0 = b2[cc], b1v = b2[cc + 1];
            int r0 = rm + mi * 16 + gr;
            buf[r0 * 65 + cc] = acc2[mi][ni][0] + b0;
            buf[r0 * 65 + cc + 1] = acc2[mi][ni][1] + b1v;
            buf[(r0 + 8) * 65 + cc] = acc2[mi][ni][2] + b0;
            buf[(r0 + 8) * 65 + cc + 1] = acc2[mi][ni][3] + b1v;
        }
    __syncthreads();

#pragma unroll
    for (int rr = 0; rr < 16; rr++) {
        int row = w * 16 + rr;
        size_t go = (size_t)(row0 + row) * 64;
        float y0 = buf[row * 65 + lane] + xr0[rr];
        float y1 = buf[row * 65 + lane + 32] + xr1[rr];
        float mean = warp_sum32(y0 + y1) * (1.0f / 64.0f);
        float d0 = y0 - mean, d1 = y1 - mean;
        float var = warp_sum32(d0 * d0 + d1 * d1) * (1.0f / 64.0f);
        float inv = rsqrtf(var + 1e-5f);
        float o0 = d0 * inv * ln2_s[lane] + ln2_b[lane];
        float o1 = d1 * inv * ln2_s[lane + 32] + ln2_b[lane + 32];
        x[go + lane] = o0;
        x[go + lane + 32] = o1;
        xh[go + lane] = __float2half_rn(o0);
        xh[go + lane + 32] = __float2half_rn(o1);
    }
}

// ---------------- head ----------------
__global__ void head_kernel(const float* __restrict__ x,
                            const float* __restrict__ W_head,
                            const float* __restrict__ b_head,
                            float* __restrict__ out)
{
    int b = blockIdx.x;
    int tid = threadIdx.x;  // 192
    int v = tid / 3, c = tid % 3;
    const float* row = x + ((size_t)(b * LL + (SS - 1) * VV + v)) * EE;
    float acc = b_head[c];
#pragma unroll
    for (int e = 0; e < EE; e++) acc += row[e] * W_head[e * 3 + c];
    out[b * (VV * 3) + tid] = acc;
}

// ---------------- launch ----------------
extern "C" void kernel_launch(void* const* d_in, const int* in_sizes, int n_in,
                              void* d_out, int out_size)
{
    const float* features    = (const float*)d_in[0];
    const int*   overlap_tag = (const int*)d_in[1];
    const int*   poi_id      = (const int*)d_in[2];
    const float* W_raw       = (const float*)d_in[3];
    const float* b_raw       = (const float*)d_in[4];
    const float* pos_tab     = (const float*)d_in[5];
    const float* type_tab    = (const float*)d_in[6];
    const float* poi_tab     = (const float*)d_in[7];
    const float* overlap_tab = (const float*)d_in[8];
    const float* W_comb      = (const float*)d_in[9];
    const float* b_comb      = (const float*)d_in[10];
    const float* Wqkv        = (const float*)d_in[11];
    const float* bqkv        = (const float*)d_in[12];
    const float* Wo          = (const float*)d_in[13];
    const float* bo          = (const float*)d_in[14];
    const float* ln1_s       = (const float*)d_in[15];
    const float* ln1_b       = (const float*)d_in[16];
    const float* W1          = (const float*)d_in[17];
    const float* b1          = (const float*)d_in[18];
    const float* W2          = (const float*)d_in[19];
    const float* b2          = (const float*)d_in[20];
    const float* ln2_s       = (const float*)d_in[21];
    const float* ln2_b       = (const float*)d_in[22];
    const float* W_head      = (const float*)d_in[23];
    const float* b_head      = (const float*)d_in[24];
    float* out = (float*)d_out;

    float *x;
    __half *xh, *attnh, *qkvT, *woT, *w1T, *w2T;
    unsigned char* zero;
    cudaGetSymbolAddress((void**)&x,     g_x);
    cudaGetSymbolAddress((void**)&xh,    g_xh);
    cudaGetSymbolAddress((void**)&attnh, g_attnh);
    cudaGetSymbolAddress((void**)&zero,  g_zero);
    cudaGetSymbolAddress((void**)&qkvT,  g_qkvT);
    cudaGetSymbolAddress((void**)&woT,   g_woT);
    cudaGetSymbolAddress((void**)&w1T,   g_w1T);
    cudaGetSymbolAddress((void**)&w2T,   g_w2T);

    cudaFuncSetAttribute(attn_kernel, cudaFuncAttributeMaxDynamicSharedMemorySize, ATTN_SMEM);
    cudaFuncSetAttribute(wo_ffn_fused, cudaFuncAttributeMaxDynamicSharedMemorySize, FFN_SMEM);

    prep_weights<<<dim3(256, 4), 256>>>(Wqkv, Wo, W1, W2);

    embed_kernel<<<ML, 64>>>(features, overlap_tag, poi_id, W_raw, b_raw,
                             pos_tab, type_tab, poi_tab, overlap_tab,
                             W_comb, b_comb, x, xh, zero);

    for (int l = 0; l < NL; l++) {
        attn_kernel<<<BB * HH, 1024, ATTN_SMEM>>>(
            xh, qkvT + l * 12288, bqkv + l * 192, zero, attnh);
        wo_ffn_fused<<<ML / 128, 256, FFN_SMEM>>>(
            attnh, woT + l * 4096, bo + l * EE,
            ln1_s + l * EE, ln1_b + l * EE,
            w1T + l * DFF * 64, w2T + l * DFF * 64,
            b1 + l * DFF, b2 + l * EE,
            ln2_s + l * EE, ln2_b + l * EE,
            x, xh);
    }

    head_kernel<<<BB, VV * 3>>>(x, W_head, b_head, out);
}